// round 1
// baseline (speedup 1.0000x reference)
#include <cuda_runtime.h>
#include <math.h>

// Problem constants
#define T_ 512
#define B_ 256
#define D_ 256
#define H_ 256
#define Q_ 256
#define M_ (T_*B_)        // 131072 rows (t,b)
#define MT 64             // rows per CTA
#define XS_STRIDE 260     // padded x row in smem

// Scratch (no cudaMalloc allowed)
__device__ float g_Wt[4*256*256];   // [gate][k][q]  transposed weights, 1 MB
__device__ float g_wsum[4*256];     // per-gate sum of W[:, D:] over H cols
__device__ float g_gf[4*M_];        // gate parity fractions, 2 MB
__device__ float g_hxs[M_];         // hx scalar per (t,b)
__device__ float g_hxf[B_];
__device__ float g_cxf[B_];

// ---------------------------------------------------------------------------
// K0: transpose W x-part into [k][q] layout and compute wsum[q] = sum_j W[q, D+j]
// grid: 1024 blocks (4 gates x 256 q), 256 threads (one per k)
// ---------------------------------------------------------------------------
__global__ void prep_kernel(const float* __restrict__ Wf, const float* __restrict__ Wi,
                            const float* __restrict__ Wu, const float* __restrict__ Wo)
{
    int g = blockIdx.x >> 8;
    int q = blockIdx.x & 255;
    int k = threadIdx.x;
    const float* W = (g == 0) ? Wf : (g == 1) ? Wi : (g == 2) ? Wu : Wo;

    g_Wt[(g * 256 + k) * 256 + q] = W[q * 512 + k];

    __shared__ float red[256];
    red[k] = W[q * 512 + 256 + k];
    __syncthreads();
    for (int s = 128; s > 0; s >>= 1) {
        if (k < s) red[k] += red[k + s];
        __syncthreads();
    }
    if (k == 0) g_wsum[g * 256 + q] = red[0];
}

// ---------------------------------------------------------------------------
// K1 (main): fused conv + 4-gate GEMM + threshold + prefix-parity fraction.
// CTA: 64 rows x 256 q, 256 threads as 16 rowgroups x 16 colgroups.
// Thread tile: 4 rows x 16 cols (cols strided by 16 -> conflict-free LDS).
// ---------------------------------------------------------------------------
__global__ __launch_bounds__(256, 1) void gemm_parity_kernel(
    const float* __restrict__ x,
    const float* __restrict__ bfp, const float* __restrict__ bip,
    const float* __restrict__ bup, const float* __restrict__ bop)
{
    extern __shared__ float smem[];
    float* xs    = smem;                       // MT * XS_STRIDE floats
    float* ws    = xs + MT * XS_STRIDE;        // 2 * 32 * 256 floats (double buffer)
    float* convs = ws + 2 * 32 * 256;          // 64 floats
    unsigned char* bits = (unsigned char*)(convs + 64);  // MT * 264 bytes

    const int tid = threadIdx.x;
    const int m0  = blockIdx.x * MT;

    // Load x tile (64 x 256, contiguous) into padded smem
    const float4* xblk = (const float4*)(x + (size_t)m0 * D_);
#pragma unroll
    for (int i = 0; i < 16; i++) {
        int idx = tid + i * 256;        // float4 index within tile (0..4095)
        int r = idx >> 6, c = idx & 63;
        float4 v = xblk[idx];
        *(float4*)(xs + r * XS_STRIDE + c * 4) = v;
    }
    __syncthreads();

    // conv[row] = mean of inclusive prefix-XOR of (x > 0)
    if (tid < MT) {
        const float* xr = xs + tid * XS_STRIDE;
        int par = 0, cnt = 0;
#pragma unroll 8
        for (int q = 0; q < D_; q++) {
            par ^= (xr[q] > 0.0f);
            cnt += par;
        }
        convs[tid] = (float)cnt * (1.0f / 256.0f);
    }
    __syncthreads();

    const int rowg = tid >> 4;
    const int colg = tid & 15;
    const int r0   = rowg * 4;

#pragma unroll 1
    for (int g = 0; g < 4; g++) {
        const float* Wg   = g_Wt + g * 65536;
        const float* bias = (g == 0) ? bfp : (g == 1) ? bip : (g == 2) ? bup : bop;
        const float* wsum = g_wsum + g * 256;

        float acc[4][16];
#pragma unroll
        for (int i = 0; i < 4; i++)
#pragma unroll
            for (int j = 0; j < 16; j++) acc[i][j] = 0.0f;

        // preload slab 0 (32 k x 256 q)
        {
            float4* dst = (float4*)ws;
            const float4* s4 = (const float4*)Wg;
#pragma unroll
            for (int i = 0; i < 8; i++) dst[tid + i * 256] = s4[tid + i * 256];
        }
        __syncthreads();

        int cur = 0;
        for (int ks = 0; ks < 8; ks++) {
            // prefetch next slab into the other buffer
            if (ks < 7) {
                float4* dst = (float4*)(ws + (cur ^ 1) * 8192);
                const float4* s4 = (const float4*)(Wg + (ks + 1) * 8192);
#pragma unroll
                for (int i = 0; i < 8; i++) dst[tid + i * 256] = s4[tid + i * 256];
            }
            const float* wb = ws + cur * 8192 + colg;
            const float* xk = xs + ks * 32;
#pragma unroll 4
            for (int kk = 0; kk < 32; kk++) {
                float x0 = xk[(r0 + 0) * XS_STRIDE + kk];
                float x1 = xk[(r0 + 1) * XS_STRIDE + kk];
                float x2 = xk[(r0 + 2) * XS_STRIDE + kk];
                float x3 = xk[(r0 + 3) * XS_STRIDE + kk];
                const float* wk = wb + kk * 256;
#pragma unroll
                for (int j = 0; j < 16; j++) {
                    float wv = wk[j * 16];
                    acc[0][j] = fmaf(x0, wv, acc[0][j]);
                    acc[1][j] = fmaf(x1, wv, acc[1][j]);
                    acc[2][j] = fmaf(x2, wv, acc[2][j]);
                    acc[3][j] = fmaf(x3, wv, acc[3][j]);
                }
            }
            __syncthreads();
            cur ^= 1;
        }

        // Epilogue: raw = acc + bias[q] + conv[row]*wsum[q]; bit = raw > 0.5
        float cv0 = convs[r0 + 0];
        float cv1 = convs[r0 + 1];
        float cv2 = convs[r0 + 2];
        float cv3 = convs[r0 + 3];
#pragma unroll
        for (int j = 0; j < 16; j++) {
            int q = colg + j * 16;
            float wq = wsum[q];
            float bq = bias[q];
            bits[(r0 + 0) * 264 + q] = (fmaf(cv0, wq, acc[0][j] + bq) > 0.5f);
            bits[(r0 + 1) * 264 + q] = (fmaf(cv1, wq, acc[1][j] + bq) > 0.5f);
            bits[(r0 + 2) * 264 + q] = (fmaf(cv2, wq, acc[2][j] + bq) > 0.5f);
            bits[(r0 + 3) * 264 + q] = (fmaf(cv3, wq, acc[3][j] + bq) > 0.5f);
        }
        __syncthreads();

        // Prefix-parity fraction per row over q = 0..255 (in order)
        if (tid < MT) {
            const unsigned char* br = bits + tid * 264;
            int par = 0, cnt = 0;
#pragma unroll 8
            for (int q = 0; q < Q_; q++) {
                par ^= br[q];
                cnt += par;
            }
            g_gf[g * M_ + m0 + tid] = (float)cnt * (1.0f / 256.0f);
        }
        __syncthreads();
    }
}

// ---------------------------------------------------------------------------
// K2: sequential scan over t (per batch row). State is row-constant since
// cx0 = 0 and gates are per-row scalars.
// ---------------------------------------------------------------------------
__global__ void scan_kernel(const float* __restrict__ cx0)
{
    int b = threadIdx.x;
    float cx = cx0[b * H_];   // row-constant init (zeros)
    float hx = 0.0f;
    const float* pf_ = g_gf;
    const float* pi_ = g_gf + M_;
    const float* pu_ = g_gf + 2 * M_;
    const float* po_ = g_gf + 3 * M_;
#pragma unroll 4
    for (int t = 0; t < T_; t++) {
        int m = t * B_ + b;
        float f  = 1.0f / (1.0f + expf(-pf_[m]));
        float ii = 1.0f / (1.0f + expf(-pi_[m]));
        float gg = tanhf(pu_[m]);
        float o  = 1.0f / (1.0f + expf(-po_[m]));
        cx = fmaf(f, cx, ii * gg);
        hx = o * tanhf(cx);
        g_hxs[m] = hx;
    }
    g_hxf[b] = hx;
    g_cxf[b] = cx;
}

// ---------------------------------------------------------------------------
// K3: broadcast hx scalars to the (T,B,H) output + final hx, cx tails.
// Output layout: outs (T*B*H) | hx (B*H) | cx (B*H), all float32.
// ---------------------------------------------------------------------------
__global__ void bcast_kernel(float4* __restrict__ out)
{
    unsigned int i = blockIdx.x * 256u + threadIdx.x;   // float4 index
    const unsigned int OUTS_F4 = (unsigned int)(T_) * B_ * (H_ / 4);  // 8388608
    float v;
    if (i < OUTS_F4) {
        v = g_hxs[i >> 6];            // H/4 = 64 float4 per (t,b)
    } else {
        unsigned int j = i - OUTS_F4;
        if (j < (unsigned int)(B_ * H_ / 4)) v = g_hxf[j >> 6];
        else                                 v = g_cxf[(j - B_ * H_ / 4) >> 6];
    }
    out[i] = make_float4(v, v, v, v);
}

// ---------------------------------------------------------------------------
extern "C" void kernel_launch(void* const* d_in, const int* in_sizes, int n_in,
                              void* d_out, int out_size)
{
    const float* x   = (const float*)d_in[0];
    // d_in[1] = hx0 (unused: outs are post-step hx)
    const float* cx0 = (const float*)d_in[2];
    const float* Wf  = (const float*)d_in[3];
    const float* bf_ = (const float*)d_in[4];
    const float* Wi  = (const float*)d_in[5];
    const float* bi_ = (const float*)d_in[6];
    const float* Wu  = (const float*)d_in[7];
    const float* bu_ = (const float*)d_in[8];
    const float* Wo  = (const float*)d_in[9];
    const float* bo_ = (const float*)d_in[10];

    const int smem_bytes = (MT * XS_STRIDE + 2 * 32 * 256 + 64) * 4 + MT * 264;  // 149248
    cudaFuncSetAttribute(gemm_parity_kernel,
                         cudaFuncAttributeMaxDynamicSharedMemorySize, smem_bytes);

    prep_kernel<<<1024, 256>>>(Wf, Wi, Wu, Wo);
    gemm_parity_kernel<<<M_ / MT, 256, smem_bytes>>>(x, bf_, bi_, bu_, bo_);
    scan_kernel<<<1, B_>>>(cx0);

    const unsigned int total_f4 = (unsigned int)(T_) * B_ * (H_ / 4) + 2u * (B_ * H_ / 4);
    bcast_kernel<<<total_f4 / 256, 256>>>((float4*)d_out);
}

// round 3
// speedup vs baseline: 2.5551x; 2.5551x over previous
#include <cuda_runtime.h>
#include <cuda_bf16.h>
#include <math.h>
#include <stdint.h>

#define T_ 512
#define B_ 256
#define D_ 256
#define H_ 256
#define Q_ 256
#define M_ (T_*B_)
#define MT 128
#define NTILES (M_/MT)

// tcgen05 only exists in the arch-specific ('a') compilation pass.
#if defined(__CUDA_ARCH__) && (defined(__CUDA_ARCH_FEAT_SM103_ALL) || defined(__CUDA_ARCH_FEAT_SM100_ALL) || defined(__CUDA_ARCH_FEAT_SM110_ALL) || (defined(__CUDA_ARCH_SPECIFIC__) && (__CUDA_ARCH_SPECIFIC__ == 1030 || __CUDA_ARCH_SPECIFIC__ == 1000)))
#define USE_TCGEN05 1
#else
#define USE_TCGEN05 0
#endif

// idesc: dtype F32, atype/btype BF16, N=256, M=128
#define IDESC ((1u<<4)|(1u<<7)|(1u<<10)|((256u/8)<<17)|((128u/16)<<24))

// ---- scratch (no cudaMalloc allowed) ----
__device__ float g_wsum[4*256];
__device__ float g_Wt[4*256*256];                        // fp32 [gate][k][q] (fallback path)
__device__ float g_gf[4*M_];
__device__ float g_hxs[M_];
__device__ float g_hxf[B_];
__device__ float g_cxf[B_];
__device__ __align__(1024) uint8_t g_Wb[4*3*4*32768];    // [gate][split][kc] 32KB swizzled bf16 chunks

// ---- smem offsets for tcgen05 path (relative to 1024-aligned base) ----
#define SM_A      0
#define SM_B0     131072
#define SM_B1     (131072+32768)
#define SM_CONV   (131072+65536)        // 128 floats
#define SM_BIAS   (SM_CONV+512)         // 256 floats
#define SM_WSUM   (SM_BIAS+1024)        // 256 floats
#define SM_TPTR   (SM_WSUM+1024)
#define SM_MBAR   (SM_TPTR+16)
#define SMEM_DYN  200704

// ============================ common helpers ============================
__device__ __forceinline__ uint32_t smem_u32(const void* p){
    uint32_t a;
    asm("{ .reg .u64 t; cvta.to.shared.u64 t, %1; cvt.u32.u64 %0, t; }" : "=r"(a) : "l"(p));
    return a;
}
__device__ __forceinline__ uint32_t pack_bf(__nv_bfloat16 a, __nv_bfloat16 b){
    uint16_t ua = *reinterpret_cast<uint16_t*>(&a);
    uint16_t ub = *reinterpret_cast<uint16_t*>(&b);
    return (uint32_t)ua | ((uint32_t)ub << 16);
}
__device__ __forceinline__ void split3(float v, __nv_bfloat16& s0, __nv_bfloat16& s1, __nv_bfloat16& s2){
    s0 = __float2bfloat16(v);
    float r1 = v - __bfloat162float(s0);
    s1 = __float2bfloat16(r1);
    float r2 = r1 - __bfloat162float(s1);
    s2 = __float2bfloat16(r2);
}

#if USE_TCGEN05
// ============================ tcgen05 PTX helpers ============================
__device__ __forceinline__ uint32_t elect_one(){
    uint32_t p;
    asm volatile("{\n\t.reg .pred p;\n\telect.sync _|p, 0xFFFFFFFF;\n\tselp.b32 %0,1,0,p;\n\t}":"=r"(p));
    return p;
}
#define MBAR_INIT(a,c) asm volatile("mbarrier.init.shared.b64 [%0], %1;"::"r"(a),"r"(c):"memory")
#define MBAR_INVAL(a)  asm volatile("mbarrier.inval.shared.b64 [%0];"::"r"(a):"memory")
#define MBAR_WAIT(a,ph) do{ uint32_t _m=(a),_p=(ph),_d; \
    asm volatile("{\n\t.reg .pred p;\n\tmbarrier.try_wait.parity.acquire.cta.shared::cta.b64 p,[%1],%2;\n\tselp.b32 %0,1,0,p;\n\t}":"=r"(_d):"r"(_m),"r"(_p):"memory"); \
    if(!_d){ asm volatile("{\n\t.reg .pred P1;\n\tWL_%=:\n\tmbarrier.try_wait.parity.acquire.cta.shared::cta.b64 P1,[%0],%1,0x989680;\n\t@P1 bra.uni WD_%=;\n\tbra.uni WL_%=;\n\tWD_%=:\n\t}"::"r"(_m),"r"(_p):"memory"); } }while(0)

#define TC_ALLOC(sa,n)   asm volatile("tcgen05.alloc.cta_group::1.sync.aligned.shared::cta.b32 [%0], %1;"::"r"(sa),"r"(n):"memory")
#define TC_DEALLOC(t,n)  asm volatile("tcgen05.dealloc.cta_group::1.sync.aligned.b32 %0, %1;"::"r"(t),"r"(n))
#define TC_COMMIT(a)     asm volatile("tcgen05.commit.cta_group::1.mbarrier::arrive::one.shared::cluster.b64 [%0];"::"r"(a):"memory")
#define TC_FENCE_BEFORE() asm volatile("tcgen05.fence::before_thread_sync;":::"memory")
#define TC_FENCE_AFTER()  asm volatile("tcgen05.fence::after_thread_sync;":::"memory")
#define TC_WAIT_LD()     asm volatile("tcgen05.wait::ld.sync.aligned;":::"memory")
#define TC_WAIT_ST()     asm volatile("tcgen05.wait::st.sync.aligned;":::"memory")
#define FENCE_PROXY()    asm volatile("fence.proxy.async.shared::cta;":::"memory")

#define TC_LD_X32(r, a) \
    asm volatile("tcgen05.ld.sync.aligned.32x32b.x32.b32 " \
        "{%0,%1,%2,%3,%4,%5,%6,%7,%8,%9,%10,%11,%12,%13,%14,%15," \
        "%16,%17,%18,%19,%20,%21,%22,%23,%24,%25,%26,%27,%28,%29,%30,%31}, [%32];" \
        : "=r"((r)[0]),"=r"((r)[1]),"=r"((r)[2]),"=r"((r)[3]),"=r"((r)[4]),"=r"((r)[5]),"=r"((r)[6]),"=r"((r)[7]), \
          "=r"((r)[8]),"=r"((r)[9]),"=r"((r)[10]),"=r"((r)[11]),"=r"((r)[12]),"=r"((r)[13]),"=r"((r)[14]),"=r"((r)[15]), \
          "=r"((r)[16]),"=r"((r)[17]),"=r"((r)[18]),"=r"((r)[19]),"=r"((r)[20]),"=r"((r)[21]),"=r"((r)[22]),"=r"((r)[23]), \
          "=r"((r)[24]),"=r"((r)[25]),"=r"((r)[26]),"=r"((r)[27]),"=r"((r)[28]),"=r"((r)[29]),"=r"((r)[30]),"=r"((r)[31]) \
        : "r"(a))

#define TC_ST_X32(a, r) \
    asm volatile("tcgen05.st.sync.aligned.32x32b.x32.b32 [%0], " \
        "{%1,%2,%3,%4,%5,%6,%7,%8,%9,%10,%11,%12,%13,%14,%15,%16," \
        "%17,%18,%19,%20,%21,%22,%23,%24,%25,%26,%27,%28,%29,%30,%31,%32};" \
        :: "r"(a), \
           "r"((r)[0]),"r"((r)[1]),"r"((r)[2]),"r"((r)[3]),"r"((r)[4]),"r"((r)[5]),"r"((r)[6]),"r"((r)[7]), \
           "r"((r)[8]),"r"((r)[9]),"r"((r)[10]),"r"((r)[11]),"r"((r)[12]),"r"((r)[13]),"r"((r)[14]),"r"((r)[15]), \
           "r"((r)[16]),"r"((r)[17]),"r"((r)[18]),"r"((r)[19]),"r"((r)[20]),"r"((r)[21]),"r"((r)[22]),"r"((r)[23]), \
           "r"((r)[24]),"r"((r)[25]),"r"((r)[26]),"r"((r)[27]),"r"((r)[28]),"r"((r)[29]),"r"((r)[30]),"r"((r)[31]) \
        : "memory")

// SW128 K-major descriptor: layout=2, version=1, SBO=64, LBO=1
static constexpr uint64_t DESC_BASE =
    (uint64_t(2)<<61) | (uint64_t(1)<<46) | (uint64_t(64)<<32) | (uint64_t(1)<<16);
__device__ __forceinline__ uint64_t make_desc(uint32_t addr){
    return DESC_BASE | (uint64_t)((addr>>4)&0x3FFF);
}
__device__ __forceinline__ void mma_ss(uint32_t d, uint64_t a, uint64_t b, uint32_t en){
    asm volatile("{\n\t.reg .pred p;\n\tsetp.ne.u32 p, %4, 0;\n\t"
        "tcgen05.mma.cta_group::1.kind::f16 [%0], %1, %2, %3, {%5,%5,%5,%5}, p;\n\t}"
        :: "r"(d), "l"(a), "l"(b), "r"(IDESC), "r"(en), "r"(0u) : "memory");
}
__device__ __forceinline__ void mma_ts(uint32_t d, uint32_t a_tmem, uint64_t b, uint32_t en){
    asm volatile("{\n\t.reg .pred p;\n\tsetp.ne.u32 p, %4, 0;\n\t"
        "tcgen05.mma.cta_group::1.kind::f16 [%0], [%1], %2, %3, {%5,%5,%5,%5}, p;\n\t}"
        :: "r"(d), "r"(a_tmem), "l"(b), "r"(IDESC), "r"(en), "r"(0u) : "memory");
}
#endif // USE_TCGEN05

// ============================ K0: weight prep ============================
__global__ void prep_kernel(const float* __restrict__ Wf, const float* __restrict__ Wi,
                            const float* __restrict__ Wu, const float* __restrict__ Wo)
{
    int g = blockIdx.x >> 8;
    int q = blockIdx.x & 255;
    int k = threadIdx.x;
    const float* W = (g==0)?Wf:(g==1)?Wi:(g==2)?Wu:Wo;

    float w = W[q*512 + k];
    g_Wt[(g*256 + k)*256 + q] = w;                       // fp32 for fallback

    __nv_bfloat16 w0,w1,w2; split3(w, w0, w1, w2);
    uint32_t off = (uint32_t)((q>>3)*1024 + (q&7)*128 + (k&63)*2);
    off ^= (off>>3) & 0x70;
    int kc = k >> 6;
    *(__nv_bfloat16*)(g_Wb + ((size_t)((g*3+0)*4 + kc))*32768 + off) = w0;
    *(__nv_bfloat16*)(g_Wb + ((size_t)((g*3+1)*4 + kc))*32768 + off) = w1;
    *(__nv_bfloat16*)(g_Wb + ((size_t)((g*3+2)*4 + kc))*32768 + off) = w2;

    __shared__ float red[256];
    red[k] = W[q*512 + 256 + k];
    __syncthreads();
    for (int s = 128; s > 0; s >>= 1) {
        if (k < s) red[k] += red[k+s];
        __syncthreads();
    }
    if (k == 0) g_wsum[g*256 + q] = red[0];
}

// ============================ K1: GEMM + parity ============================
__device__ __forceinline__ void copy32k(const uint8_t* __restrict__ src, uint8_t* dst, int tid){
    const uint4* s = (const uint4*)src;
    uint4* d = (uint4*)dst;
#pragma unroll
    for (int i = 0; i < 8; i++) d[tid + i*256] = s[tid + i*256];
}

__global__ __launch_bounds__(256, 1) void qmma_kernel(
    const float* __restrict__ x,
    const float* __restrict__ bfp, const float* __restrict__ bip,
    const float* __restrict__ bup, const float* __restrict__ bop)
{
    extern __shared__ uint8_t smem_raw[];
    const int tid = threadIdx.x;
    const int m0  = blockIdx.x * MT;

#if USE_TCGEN05
    uint32_t sraw = smem_u32(smem_raw);
    uint32_t sb   = (sraw + 1023u) & ~1023u;
    uint8_t* sm   = smem_raw + (sb - sraw);
    const int wid = tid >> 5;
    const int lid = tid & 31;

    if (wid == 0) TC_ALLOC(sb + SM_TPTR, 512);
    if (tid == 0) { MBAR_INIT(sb+SM_MBAR, 1); MBAR_INIT(sb+SM_MBAR+8, 1); }
    __syncthreads();
    uint32_t tmem;
    asm volatile("ld.shared.b32 %0, [%1];" : "=r"(tmem) : "r"(sb + SM_TPTR));
    const uint32_t D_T  = tmem;        // D: cols 0..255
    const uint32_t X2_T = tmem + 256;  // x2: cols 256..383

    // ---- prologue: load x tile, split to bf16x3; x0|x1 -> A smem, x2 -> staging ----
    const float4* xr = (const float4*)(x + (size_t)m0 * D_);
#pragma unroll 4
    for (int i = 0; i < 32; i++) {
        int f4 = tid + i*256;
        int r = f4 >> 6;
        int c = (f4 & 63) * 4;
        float4 v = xr[f4];
        __nv_bfloat16 a0,a1,a2,a3, b0,b1,b2,b3, c0,c1,c2,c3;
        split3(v.x, a0,b0,c0); split3(v.y, a1,b1,c1);
        split3(v.z, a2,b2,c2); split3(v.w, a3,b3,c3);
        uint32_t off = (uint32_t)(((r>>3) + (c>>6)*16)*1024 + (r&7)*128 + (c&63)*2);
        uint32_t sw  = off ^ ((off>>3) & 0x70);
        *(uint32_t*)(sm + SM_A + sw)           = pack_bf(a0,a1);
        *(uint32_t*)(sm + SM_A + sw + 4)       = pack_bf(a2,a3);
        *(uint32_t*)(sm + SM_A + sw + 65536)   = pack_bf(b0,b1);
        *(uint32_t*)(sm + SM_A + sw + 65540)   = pack_bf(b2,b3);
        *(uint32_t*)(sm + SM_B0 + (size_t)(r*256 + c)*2)     = pack_bf(c0,c1);
        *(uint32_t*)(sm + SM_B0 + (size_t)(r*256 + c)*2 + 4) = pack_bf(c2,c3);
    }
    __syncthreads();

    // warps 0-3: x2 staging -> TMEM ; warps 4-7: conv per row
    if (wid < 4) {
        uint32_t woff = ((uint32_t)wid) << 21;
#pragma unroll
        for (int cc = 0; cc < 4; cc++) {
            uint32_t r32[32];
#pragma unroll
            for (int j = 0; j < 32; j++)
                r32[j] = *(uint32_t*)(sm + SM_B0 + (size_t)tid*512 + cc*128 + j*4);
            TC_ST_X32(X2_T + cc*32 + woff, r32);
        }
        TC_WAIT_ST();
        TC_FENCE_BEFORE();
    } else {
        int r = tid - 128;
        const float4* xv = (const float4*)(x + (size_t)(m0 + r) * D_);
        int par = 0, cnt = 0;
#pragma unroll 4
        for (int q4 = 0; q4 < 64; q4++) {
            float4 v = xv[q4];
            par ^= (v.x > 0.0f); cnt += par;
            par ^= (v.y > 0.0f); cnt += par;
            par ^= (v.z > 0.0f); cnt += par;
            par ^= (v.w > 0.0f); cnt += par;
        }
        ((float*)(sm + SM_CONV))[r] = (float)cnt * (1.0f/256.0f);
    }
    FENCE_PROXY();
    __syncthreads();

    const uint64_t adesc  = make_desc(sb + SM_A);
    const uint64_t bdesc0 = make_desc(sb + SM_B0);
    const uint64_t bdesc1 = make_desc(sb + SM_B1);

    int phase0 = 0, phase1 = 0;
    bool pend0 = false, pend1 = false;

    for (int g = 0; g < 4; g++) {
        const float* bias = (g==0)?bfp:(g==1)?bip:(g==2)?bup:bop;
        ((float*)(sm + SM_BIAS))[tid] = bias[tid];
        ((float*)(sm + SM_WSUM))[tid] = g_wsum[g*256 + tid];

        if (pend0) { MBAR_WAIT(sb+SM_MBAR, phase0); phase0 ^= 1; pend0 = false; }
        copy32k(g_Wb + ((size_t)(g*3+0)*4 + 0)*32768, sm + SM_B0, tid);
        FENCE_PROXY();
        __syncthreads();

        uint32_t en = 0;
        for (int j = 0; j < 12; j++) {
            int sbi = j >> 2, kc = j & 3, buf = j & 1;
            int npairs = 3 - sbi;
            if (wid == 0 && elect_one()) {
                TC_FENCE_AFTER();
                uint64_t bd = buf ? bdesc1 : bdesc0;
                for (int ap = 0; ap < npairs; ap++) {
                    if (ap == 2) {
#pragma unroll
                        for (int t = 0; t < 4; t++) {
                            mma_ts(D_T, X2_T + (kc*4 + t)*8, bd + t*2, en); en = 1;
                        }
                    } else {
#pragma unroll
                        for (int t = 0; t < 4; t++) {
                            mma_ss(D_T, adesc + (uint64_t)((ap*4 + kc)*1024 + t*2), bd + t*2, en); en = 1;
                        }
                    }
                }
                TC_COMMIT(sb + SM_MBAR + buf*8);
            }
            if (buf == 0) pend0 = true; else pend1 = true;

            if (j < 11) {
                int b2 = buf ^ 1;
                if (b2 == 0) { if (pend0) { MBAR_WAIT(sb+SM_MBAR,   phase0); phase0 ^= 1; pend0 = false; } }
                else         { if (pend1) { MBAR_WAIT(sb+SM_MBAR+8, phase1); phase1 ^= 1; pend1 = false; } }
                int j2 = j + 1;
                size_t ci2 = (size_t)(g*3 + (j2>>2))*4 + (j2 & 3);
                copy32k(g_Wb + ci2*32768, sm + (b2 ? SM_B1 : SM_B0), tid);
                FENCE_PROXY();
            }
            __syncthreads();
        }
        if (pend0) { MBAR_WAIT(sb+SM_MBAR,   phase0); phase0 ^= 1; pend0 = false; }
        if (pend1) { MBAR_WAIT(sb+SM_MBAR+8, phase1); phase1 ^= 1; pend1 = false; }
        TC_FENCE_AFTER();

        // ---- epilogue: threshold + prefix-parity fraction ----
        if (wid < 4) {
            const float cv = ((float*)(sm + SM_CONV))[wid*32 + lid];
            const float* bias_s = (const float*)(sm + SM_BIAS);
            const float* wsum_s = (const float*)(sm + SM_WSUM);
            int par = 0, cnt = 0;
#pragma unroll
            for (int cc = 0; cc < 8; cc++) {
                uint32_t r[32];
                TC_LD_X32(r, D_T + cc*32);
                TC_WAIT_LD();
                uint32_t word = 0;
#pragma unroll
                for (int jj = 0; jj < 32; jj++) {
                    int q = cc*32 + jj;
                    float raw = __uint_as_float(r[jj]) + bias_s[q] + cv * wsum_s[q];
                    word |= (raw > 0.5f) ? (1u << jj) : 0u;
                }
                uint32_t p = word;
                p ^= p << 1; p ^= p << 2; p ^= p << 4; p ^= p << 8; p ^= p << 16;
                cnt += __popc(p ^ (par ? 0xFFFFFFFFu : 0u));
                par ^= (int)(p >> 31);
            }
            g_gf[g*M_ + m0 + wid*32 + lid] = (float)cnt * (1.0f/256.0f);
            TC_FENCE_BEFORE();
        }
        __syncthreads();
    }

    if (tid == 0) { MBAR_INVAL(sb+SM_MBAR); MBAR_INVAL(sb+SM_MBAR+8); }
    __syncthreads();
    if (wid == 0) TC_DEALLOC(tmem, 512);

#else  // ======================= fp32 fallback (compute_103 pass) =======================
    float* xs    = (float*)smem_raw;                 // 128 x 260
    float* ws    = (float*)(smem_raw + 133120);      // 32 x 256
    float* convs = (float*)(smem_raw + 165888);      // 128
    unsigned char* bits = smem_raw + 166400;         // 64 x 264

    const float4* xblk = (const float4*)(x + (size_t)m0 * D_);
#pragma unroll 4
    for (int i = 0; i < 32; i++) {
        int idx = tid + i*256;
        int r = idx >> 6, c = idx & 63;
        *(float4*)(xs + r*260 + c*4) = xblk[idx];
    }
    __syncthreads();

    if (tid < 128) {
        const float* xrow = xs + tid*260;
        int par = 0, cnt = 0;
#pragma unroll 8
        for (int q = 0; q < D_; q++) { par ^= (xrow[q] > 0.0f); cnt += par; }
        convs[tid] = (float)cnt * (1.0f/256.0f);
    }
    __syncthreads();

    const int rowg = tid >> 4;
    const int colg = tid & 15;
    const int r0   = rowg * 4;

    for (int g = 0; g < 4; g++) {
        const float* bias = (g==0)?bfp:(g==1)?bip:(g==2)?bup:bop;
        const float* wsum = g_wsum + g*256;

        for (int rh = 0; rh < 2; rh++) {
            float acc[4][16];
#pragma unroll
            for (int i = 0; i < 4; i++)
#pragma unroll
                for (int j = 0; j < 16; j++) acc[i][j] = 0.0f;

            for (int ks = 0; ks < 8; ks++) {
                float4* d = (float4*)ws;
                const float4* s = (const float4*)(g_Wt + g*65536 + ks*8192);
#pragma unroll
                for (int i = 0; i < 8; i++) d[tid + i*256] = s[tid + i*256];
                __syncthreads();
                const float* xk = xs + (rh*64 + r0)*260 + ks*32;
#pragma unroll 4
                for (int kk = 0; kk < 32; kk++) {
                    float x0 = xk[0*260 + kk];
                    float x1 = xk[1*260 + kk];
                    float x2 = xk[2*260 + kk];
                    float x3 = xk[3*260 + kk];
                    const float* wk = ws + kk*256 + colg;
#pragma unroll
                    for (int j = 0; j < 16; j++) {
                        float wv = wk[j*16];
                        acc[0][j] = fmaf(x0, wv, acc[0][j]);
                        acc[1][j] = fmaf(x1, wv, acc[1][j]);
                        acc[2][j] = fmaf(x2, wv, acc[2][j]);
                        acc[3][j] = fmaf(x3, wv, acc[3][j]);
                    }
                }
                __syncthreads();
            }

            float cv0 = convs[rh*64 + r0 + 0];
            float cv1 = convs[rh*64 + r0 + 1];
            float cv2 = convs[rh*64 + r0 + 2];
            float cv3 = convs[rh*64 + r0 + 3];
#pragma unroll
            for (int j = 0; j < 16; j++) {
                int q = colg + j*16;
                float wq = wsum[q];
                float bq = bias[q];
                bits[(r0+0)*264 + q] = (fmaf(cv0, wq, acc[0][j] + bq) > 0.5f);
                bits[(r0+1)*264 + q] = (fmaf(cv1, wq, acc[1][j] + bq) > 0.5f);
                bits[(r0+2)*264 + q] = (fmaf(cv2, wq, acc[2][j] + bq) > 0.5f);
                bits[(r0+3)*264 + q] = (fmaf(cv3, wq, acc[3][j] + bq) > 0.5f);
            }
            __syncthreads();

            if (tid < 64) {
                const unsigned char* br = bits + tid*264;
                int par = 0, cnt = 0;
#pragma unroll 8
                for (int q = 0; q < Q_; q++) { par ^= br[q]; cnt += par; }
                g_gf[g*M_ + m0 + rh*64 + tid] = (float)cnt * (1.0f/256.0f);
            }
            __syncthreads();
        }
    }
#endif
}

// ============================ K2: scalar scan ============================
__global__ void scan_kernel(const float* __restrict__ cx0)
{
    int b = threadIdx.x;
    float cx = cx0[b * H_];
    float hx = 0.0f;
    const float* pf_ = g_gf;
    const float* pi_ = g_gf + M_;
    const float* pu_ = g_gf + 2*M_;
    const float* po_ = g_gf + 3*M_;
#pragma unroll 4
    for (int t = 0; t < T_; t++) {
        int m = t*B_ + b;
        float f  = 1.0f / (1.0f + expf(-pf_[m]));
        float ii = 1.0f / (1.0f + expf(-pi_[m]));
        float gg = tanhf(pu_[m]);
        float o  = 1.0f / (1.0f + expf(-po_[m]));
        cx = fmaf(f, cx, ii * gg);
        hx = o * tanhf(cx);
        g_hxs[m] = hx;
    }
    g_hxf[b] = hx;
    g_cxf[b] = cx;
}

// ============================ K3: broadcast ============================
__global__ void bcast_kernel(float4* __restrict__ out)
{
    unsigned int i = blockIdx.x * 256u + threadIdx.x;
    const unsigned int OUTS_F4 = (unsigned int)(T_) * B_ * (H_/4);
    float v;
    if (i < OUTS_F4) {
        v = g_hxs[i >> 6];
    } else {
        unsigned int j = i - OUTS_F4;
        if (j < (unsigned int)(B_*H_/4)) v = g_hxf[j >> 6];
        else                             v = g_cxf[(j - B_*H_/4) >> 6];
    }
    out[i] = make_float4(v, v, v, v);
}

// ============================ launch ============================
extern "C" void kernel_launch(void* const* d_in, const int* in_sizes, int n_in,
                              void* d_out, int out_size)
{
    const float* x   = (const float*)d_in[0];
    const float* cx0 = (const float*)d_in[2];
    const float* Wf  = (const float*)d_in[3];
    const float* bf_ = (const float*)d_in[4];
    const float* Wi  = (const float*)d_in[5];
    const float* bi_ = (const float*)d_in[6];
    const float* Wu  = (const float*)d_in[7];
    const float* bu_ = (const float*)d_in[8];
    const float* Wo  = (const float*)d_in[9];
    const float* bo_ = (const float*)d_in[10];

    cudaFuncSetAttribute(qmma_kernel, cudaFuncAttributeMaxDynamicSharedMemorySize, SMEM_DYN);

    prep_kernel<<<1024, 256>>>(Wf, Wi, Wu, Wo);
    qmma_kernel<<<NTILES, 256, SMEM_DYN>>>(x, bf_, bi_, bu_, bo_);
    scan_kernel<<<1, B_>>>(cx0);

    const unsigned int total_f4 = (unsigned int)(T_) * B_ * (H_/4) + 2u * (B_*H_/4);
    bcast_kernel<<<total_f4 / 256, 256>>>((float4*)d_out);
}

// round 4
// speedup vs baseline: 2.6748x; 1.0469x over previous
#include <cuda_runtime.h>
#include <cuda_bf16.h>
#include <math.h>
#include <stdint.h>

#define T_ 512
#define B_ 256
#define D_ 256
#define H_ 256
#define Q_ 256
#define M_ (T_*B_)
#define MT 128
#define NTILES (M_/MT)

// tcgen05 only exists in the arch-specific ('a') compilation pass.
#if defined(__CUDA_ARCH__) && (defined(__CUDA_ARCH_FEAT_SM103_ALL) || defined(__CUDA_ARCH_FEAT_SM100_ALL) || defined(__CUDA_ARCH_FEAT_SM110_ALL) || (defined(__CUDA_ARCH_SPECIFIC__) && (__CUDA_ARCH_SPECIFIC__ == 1030 || __CUDA_ARCH_SPECIFIC__ == 1000)))
#define USE_TCGEN05 1
#else
#define USE_TCGEN05 0
#endif

// idesc: dtype F32, atype/btype BF16, N=256, M=128
#define IDESC ((1u<<4)|(1u<<7)|(1u<<10)|((256u/8)<<17)|((128u/16)<<24))

// ---- scratch (no cudaMalloc allowed) ----
__device__ float g_wsum[4*256];
__device__ float g_Wt[4*256*256];                        // fp32 [gate][k][q] (fallback path)
__device__ float g_gf[4*M_];
__device__ float g_hxs[M_];
__device__ float g_hxf[B_];
__device__ float g_cxf[B_];
__device__ __align__(1024) uint8_t g_Wb[4*3*4*32768];    // [gate][split][kc] 32KB swizzled bf16 chunks

// ---- smem offsets (relative to 1024-aligned base) ----
#define SM_A      0                      // 65536 : x0 SW128
#define SM_W      65536                  // 4 x 32768 ring (also x1/x2 staging in prologue)
#define SM_CONV   196608                 // 128 floats
#define SM_THR    197120                 // 4*256 floats  (0.5 - bias)
#define SM_WS2    201216                 // 4*256 floats  (wsum)
#define SM_TPTR   205312
#define SM_BAR    205328                 // full[4] empty[4] epi dfree
#define SMEM_DYN  206848

#define BAR_FULL(s)  (sb + SM_BAR + (s)*8)
#define BAR_EMPTY(s) (sb + SM_BAR + 32 + (s)*8)
#define BAR_EPI      (sb + SM_BAR + 64)
#define BAR_DFREE    (sb + SM_BAR + 72)

// ============================ common helpers ============================
__device__ __forceinline__ uint32_t smem_u32(const void* p){
    uint32_t a;
    asm("{ .reg .u64 t; cvta.to.shared.u64 t, %1; cvt.u32.u64 %0, t; }" : "=r"(a) : "l"(p));
    return a;
}
__device__ __forceinline__ uint32_t pack_bf(__nv_bfloat16 a, __nv_bfloat16 b){
    uint16_t ua = *reinterpret_cast<uint16_t*>(&a);
    uint16_t ub = *reinterpret_cast<uint16_t*>(&b);
    return (uint32_t)ua | ((uint32_t)ub << 16);
}
__device__ __forceinline__ void split3(float v, __nv_bfloat16& s0, __nv_bfloat16& s1, __nv_bfloat16& s2){
    s0 = __float2bfloat16(v);
    float r1 = v - __bfloat162float(s0);
    s1 = __float2bfloat16(r1);
    float r2 = r1 - __bfloat162float(s1);
    s2 = __float2bfloat16(r2);
}

#if USE_TCGEN05
// ============================ tcgen05 PTX helpers ============================
__device__ __forceinline__ uint32_t elect_one(){
    uint32_t p;
    asm volatile("{\n\t.reg .pred p;\n\telect.sync _|p, 0xFFFFFFFF;\n\tselp.b32 %0,1,0,p;\n\t}":"=r"(p));
    return p;
}
#define MBAR_INIT(a,c) asm volatile("mbarrier.init.shared.b64 [%0], %1;"::"r"(a),"r"(c):"memory")
#define MBAR_INVAL(a)  asm volatile("mbarrier.inval.shared.b64 [%0];"::"r"(a):"memory")
#define MBAR_ARRIVE(a) asm volatile("mbarrier.arrive.shared.b64 _, [%0];"::"r"(a):"memory")
#define MBAR_WAIT(a,ph) do{ uint32_t _m=(a),_p=(ph),_d; \
    asm volatile("{\n\t.reg .pred p;\n\tmbarrier.try_wait.parity.acquire.cta.shared::cta.b64 p,[%1],%2;\n\tselp.b32 %0,1,0,p;\n\t}":"=r"(_d):"r"(_m),"r"(_p):"memory"); \
    if(!_d){ asm volatile("{\n\t.reg .pred P1;\n\tWL_%=:\n\tmbarrier.try_wait.parity.acquire.cta.shared::cta.b64 P1,[%0],%1,0x989680;\n\t@P1 bra.uni WD_%=;\n\tbra.uni WL_%=;\n\tWD_%=:\n\t}"::"r"(_m),"r"(_p):"memory"); } }while(0)
#define MBAR_EXPECT_TX(a,n) asm volatile("mbarrier.arrive.expect_tx.shared.b64 _, [%0], %1;"::"r"(a),"r"(n):"memory")

#define TC_ALLOC(sa,n)   asm volatile("tcgen05.alloc.cta_group::1.sync.aligned.shared::cta.b32 [%0], %1;"::"r"(sa),"r"(n):"memory")
#define TC_DEALLOC(t,n)  asm volatile("tcgen05.dealloc.cta_group::1.sync.aligned.b32 %0, %1;"::"r"(t),"r"(n))
#define TC_COMMIT(a)     asm volatile("tcgen05.commit.cta_group::1.mbarrier::arrive::one.shared::cluster.b64 [%0];"::"r"(a):"memory")
#define TC_FENCE_BEFORE() asm volatile("tcgen05.fence::before_thread_sync;":::"memory")
#define TC_FENCE_AFTER()  asm volatile("tcgen05.fence::after_thread_sync;":::"memory")
#define TC_WAIT_LD()     asm volatile("tcgen05.wait::ld.sync.aligned;":::"memory")
#define TC_WAIT_ST()     asm volatile("tcgen05.wait::st.sync.aligned;":::"memory")
#define FENCE_PROXY()    asm volatile("fence.proxy.async.shared::cta;":::"memory")

#define TC_LD_X32(r, a) \
    asm volatile("tcgen05.ld.sync.aligned.32x32b.x32.b32 " \
        "{%0,%1,%2,%3,%4,%5,%6,%7,%8,%9,%10,%11,%12,%13,%14,%15," \
        "%16,%17,%18,%19,%20,%21,%22,%23,%24,%25,%26,%27,%28,%29,%30,%31}, [%32];" \
        : "=r"((r)[0]),"=r"((r)[1]),"=r"((r)[2]),"=r"((r)[3]),"=r"((r)[4]),"=r"((r)[5]),"=r"((r)[6]),"=r"((r)[7]), \
          "=r"((r)[8]),"=r"((r)[9]),"=r"((r)[10]),"=r"((r)[11]),"=r"((r)[12]),"=r"((r)[13]),"=r"((r)[14]),"=r"((r)[15]), \
          "=r"((r)[16]),"=r"((r)[17]),"=r"((r)[18]),"=r"((r)[19]),"=r"((r)[20]),"=r"((r)[21]),"=r"((r)[22]),"=r"((r)[23]), \
          "=r"((r)[24]),"=r"((r)[25]),"=r"((r)[26]),"=r"((r)[27]),"=r"((r)[28]),"=r"((r)[29]),"=r"((r)[30]),"=r"((r)[31]) \
        : "r"(a))

#define TC_ST_X32(a, r) \
    asm volatile("tcgen05.st.sync.aligned.32x32b.x32.b32 [%0], " \
        "{%1,%2,%3,%4,%5,%6,%7,%8,%9,%10,%11,%12,%13,%14,%15,%16," \
        "%17,%18,%19,%20,%21,%22,%23,%24,%25,%26,%27,%28,%29,%30,%31,%32};" \
        :: "r"(a), \
           "r"((r)[0]),"r"((r)[1]),"r"((r)[2]),"r"((r)[3]),"r"((r)[4]),"r"((r)[5]),"r"((r)[6]),"r"((r)[7]), \
           "r"((r)[8]),"r"((r)[9]),"r"((r)[10]),"r"((r)[11]),"r"((r)[12]),"r"((r)[13]),"r"((r)[14]),"r"((r)[15]), \
           "r"((r)[16]),"r"((r)[17]),"r"((r)[18]),"r"((r)[19]),"r"((r)[20]),"r"((r)[21]),"r"((r)[22]),"r"((r)[23]), \
           "r"((r)[24]),"r"((r)[25]),"r"((r)[26]),"r"((r)[27]),"r"((r)[28]),"r"((r)[29]),"r"((r)[30]),"r"((r)[31]) \
        : "memory")

// SW128 K-major descriptor: layout=2, version=1, SBO=64, LBO=1
static constexpr uint64_t DESC_BASE =
    (uint64_t(2)<<61) | (uint64_t(1)<<46) | (uint64_t(64)<<32) | (uint64_t(1)<<16);
__device__ __forceinline__ uint64_t make_desc(uint32_t addr){
    return DESC_BASE | (uint64_t)((addr>>4)&0x3FFF);
}
__device__ __forceinline__ void mma_ss(uint32_t d, uint64_t a, uint64_t b, uint32_t en){
    asm volatile("{\n\t.reg .pred p;\n\tsetp.ne.u32 p, %4, 0;\n\t"
        "tcgen05.mma.cta_group::1.kind::f16 [%0], %1, %2, %3, {%5,%5,%5,%5}, p;\n\t}"
        :: "r"(d), "l"(a), "l"(b), "r"(IDESC), "r"(en), "r"(0u) : "memory");
}
__device__ __forceinline__ void mma_ts(uint32_t d, uint32_t a_tmem, uint64_t b, uint32_t en){
    asm volatile("{\n\t.reg .pred p;\n\tsetp.ne.u32 p, %4, 0;\n\t"
        "tcgen05.mma.cta_group::1.kind::f16 [%0], [%1], %2, %3, {%5,%5,%5,%5}, p;\n\t}"
        :: "r"(d), "r"(a_tmem), "l"(b), "r"(IDESC), "r"(en), "r"(0u) : "memory");
}
__device__ __forceinline__ void bulk_ld(uint32_t dst, const void* src, uint32_t mbar){
    asm volatile("{\n\t.reg .u64 g;\n\tcvta.to.global.u64 g, %1;\n\t"
        "cp.async.bulk.shared::cluster.global.mbarrier::complete_tx::bytes [%0], [g], %2, [%3];\n\t}"
        :: "r"(dst), "l"(src), "n"(32768), "r"(mbar) : "memory");
}
#endif // USE_TCGEN05

// ============================ K0: weight prep ============================
__global__ void prep_kernel(const float* __restrict__ Wf, const float* __restrict__ Wi,
                            const float* __restrict__ Wu, const float* __restrict__ Wo)
{
    int g = blockIdx.x >> 8;
    int q = blockIdx.x & 255;
    int k = threadIdx.x;
    const float* W = (g==0)?Wf:(g==1)?Wi:(g==2)?Wu:Wo;

    float w = W[q*512 + k];
    g_Wt[(g*256 + k)*256 + q] = w;                       // fp32 for fallback

    __nv_bfloat16 w0,w1,w2; split3(w, w0, w1, w2);
    uint32_t off = (uint32_t)((q>>3)*1024 + (q&7)*128 + (k&63)*2);
    off ^= (off>>3) & 0x70;
    int kc = k >> 6;
    *(__nv_bfloat16*)(g_Wb + ((size_t)((g*3+0)*4 + kc))*32768 + off) = w0;
    *(__nv_bfloat16*)(g_Wb + ((size_t)((g*3+1)*4 + kc))*32768 + off) = w1;
    *(__nv_bfloat16*)(g_Wb + ((size_t)((g*3+2)*4 + kc))*32768 + off) = w2;

    __shared__ float red[256];
    red[k] = W[q*512 + 256 + k];
    __syncthreads();
    for (int s = 128; s > 0; s >>= 1) {
        if (k < s) red[k] += red[k+s];
        __syncthreads();
    }
    if (k == 0) g_wsum[g*256 + q] = red[0];
}

// ============================ K1: GEMM + parity ============================
__global__ __launch_bounds__(256, 1) void qmma_kernel(
    const float* __restrict__ x,
    const float* __restrict__ bfp, const float* __restrict__ bip,
    const float* __restrict__ bup, const float* __restrict__ bop)
{
    extern __shared__ uint8_t smem_raw[];
    const int tid = threadIdx.x;
    const int m0  = blockIdx.x * MT;

#if USE_TCGEN05
    uint32_t sraw = smem_u32(smem_raw);
    uint32_t sb   = (sraw + 1023u) & ~1023u;
    uint8_t* sm   = smem_raw + (sb - sraw);
    const int wid = tid >> 5;

    if (wid == 0) TC_ALLOC(sb + SM_TPTR, 512);
    if (tid == 0) {
#pragma unroll
        for (int s = 0; s < 4; s++) { MBAR_INIT(BAR_FULL(s), 1); MBAR_INIT(BAR_EMPTY(s), 1); }
        MBAR_INIT(BAR_EPI, 1);
        MBAR_INIT(BAR_DFREE, 1);
    }
    __syncthreads();
    uint32_t tmem;
    asm volatile("ld.shared.b32 %0, [%1];" : "=r"(tmem) : "r"(sb + SM_TPTR));
    const uint32_t D_T  = tmem;        // cols 0..255
    const uint32_t X1_T = tmem + 256;  // cols 256..383
    const uint32_t X2_T = tmem + 384;  // cols 384..511

    // ---- prologue: split x; x0 -> SW128 smem; x1,x2 staged linear in ring area ----
    {
        const float4* xr = (const float4*)(x + (size_t)m0 * D_);
#pragma unroll 4
        for (int i = 0; i < 32; i++) {
            int f4 = tid + i*256;
            int r = f4 >> 6;
            int c = (f4 & 63) * 4;
            float4 v = xr[f4];
            __nv_bfloat16 a0,a1,a2,a3, b0,b1,b2,b3, c0,c1,c2,c3;
            split3(v.x, a0,b0,c0); split3(v.y, a1,b1,c1);
            split3(v.z, a2,b2,c2); split3(v.w, a3,b3,c3);
            uint32_t off = (uint32_t)(((r>>3) + (c>>6)*16)*1024 + (r&7)*128 + (c&63)*2);
            uint32_t sw  = off ^ ((off>>3) & 0x70);
            *(uint32_t*)(sm + SM_A + sw)     = pack_bf(a0,a1);
            *(uint32_t*)(sm + SM_A + sw + 4) = pack_bf(a2,a3);
            *(uint32_t*)(sm + SM_W + (size_t)r*512 + c*2)             = pack_bf(b0,b1);
            *(uint32_t*)(sm + SM_W + (size_t)r*512 + c*2 + 4)         = pack_bf(b2,b3);
            *(uint32_t*)(sm + SM_W + 65536 + (size_t)r*512 + c*2)     = pack_bf(c0,c1);
            *(uint32_t*)(sm + SM_W + 65536 + (size_t)r*512 + c*2 + 4) = pack_bf(c2,c3);
        }
        // thr0 / wsum tables
        const float* bs0 = bfp;
#pragma unroll
        for (int i = 0; i < 4; i++) {
            int idx = tid + i*256;
            int g2 = idx >> 8, q = idx & 255;
            const float* bg = (g2==0)?bfp:(g2==1)?bip:(g2==2)?bup:bop;
            (void)bs0;
            ((float*)(sm + SM_THR))[idx] = 0.5f - bg[q];
            ((float*)(sm + SM_WS2))[idx] = g_wsum[idx];
        }
    }
    __syncthreads();

    if (wid < 4) {
        uint32_t woff = ((uint32_t)wid) << 21;
#pragma unroll
        for (int cc = 0; cc < 4; cc++) {
            uint32_t r32[32];
#pragma unroll
            for (int j = 0; j < 32; j++)
                r32[j] = *(uint32_t*)(sm + SM_W + (size_t)tid*512 + cc*128 + j*4);
            TC_ST_X32(X1_T + cc*32 + woff, r32);
        }
#pragma unroll
        for (int cc = 0; cc < 4; cc++) {
            uint32_t r32[32];
#pragma unroll
            for (int j = 0; j < 32; j++)
                r32[j] = *(uint32_t*)(sm + SM_W + 65536 + (size_t)tid*512 + cc*128 + j*4);
            TC_ST_X32(X2_T + cc*32 + woff, r32);
        }
        TC_WAIT_ST();
        TC_FENCE_BEFORE();
    } else {
        int r = tid - 128;
        const float4* xv = (const float4*)(x + (size_t)(m0 + r) * D_);
        int par = 0, cnt = 0;
#pragma unroll 4
        for (int q4 = 0; q4 < 64; q4++) {
            float4 v = xv[q4];
            par ^= (v.x > 0.0f); cnt += par;
            par ^= (v.y > 0.0f); cnt += par;
            par ^= (v.z > 0.0f); cnt += par;
            par ^= (v.w > 0.0f); cnt += par;
        }
        ((float*)(sm + SM_CONV))[r] = (float)cnt * (1.0f/256.0f);
    }
    FENCE_PROXY();
    __syncthreads();

    // ================= warp-specialized mainloop (no __syncthreads) =================
    if (wid == 2) {
        if ((tid & 31) == 0) {
            // -------- producer: stream 48 weight chunks through 4-slot ring --------
            int pp = 0;
            for (int c2 = 0; c2 < 48; c2++) {
                int slot = c2 & 3;
                if (c2 >= 4) {
                    MBAR_WAIT(BAR_EMPTY(slot), pp);
                    if (slot == 3) pp ^= 1;
                }
                int g = c2 / 12, idx = c2 % 12, s = idx >> 2, kc = idx & 3;
                const uint8_t* src = g_Wb + ((size_t)((g*3+s)*4 + kc))*32768;
                MBAR_EXPECT_TX(BAR_FULL(slot), 32768u);
                bulk_ld(sb + SM_W + slot*32768, src, BAR_FULL(slot));
            }
        }
    } else if (wid == 0) {
        if (elect_one()) {
            // -------- MMA issuer --------
            TC_FENCE_AFTER();
            const uint64_t adesc = make_desc(sb + SM_A);
            int cp = 0, dp = 0;
            uint32_t en = 0;
            for (int c2 = 0; c2 < 48; c2++) {
                int slot = c2 & 3;
                int g = c2/12, idx = c2%12, s = idx>>2, kc = idx&3;
                MBAR_WAIT(BAR_FULL(slot), cp);
                if (slot == 3) cp ^= 1;
                if (idx == 0) {
                    if (g > 0) { MBAR_WAIT(BAR_DFREE, dp); dp ^= 1; TC_FENCE_AFTER(); }
                    en = 0;
                }
                uint64_t bd = make_desc(sb + SM_W + slot*32768);
#pragma unroll
                for (int t = 0; t < 4; t++) { mma_ss(D_T, adesc + (uint64_t)(kc*1024 + t*2), bd + t*2, en); en = 1; }
                if (s <= 1) {
#pragma unroll
                    for (int t = 0; t < 4; t++) mma_ts(D_T, X1_T + (kc*4 + t)*8, bd + t*2, 1);
                }
                if (s == 0) {
#pragma unroll
                    for (int t = 0; t < 4; t++) mma_ts(D_T, X2_T + (kc*4 + t)*8, bd + t*2, 1);
                }
                TC_COMMIT(BAR_EMPTY(slot));
                if (idx == 11) TC_COMMIT(BAR_EPI);
            }
        }
    } else if (wid >= 4) {
        // -------- epilogue: per-gate threshold + prefix-parity --------
        const int row = tid - 128;
        const float cv = ((float*)(sm + SM_CONV))[row];
        int ep = 0;
        for (int g = 0; g < 4; g++) {
            MBAR_WAIT(BAR_EPI, ep); ep ^= 1;
            TC_FENCE_AFTER();
            const float* thr0 = (const float*)(sm + SM_THR) + g*256;
            const float* ws   = (const float*)(sm + SM_WS2) + g*256;
            int par = 0, cnt = 0;
            uint32_t rA[32], rB[32];
            TC_LD_X32(rA, D_T);
#pragma unroll
            for (int cc = 0; cc < 8; cc += 2) {
                TC_WAIT_LD();
                TC_LD_X32(rB, D_T + (cc+1)*32);
                {
                    uint32_t word = 0;
#pragma unroll
                    for (int jj = 0; jj < 32; jj++) {
                        float thr = fmaf(-cv, ws[cc*32+jj], thr0[cc*32+jj]);
                        if (__uint_as_float(rA[jj]) > thr) word |= (1u << jj);
                    }
                    uint32_t p = word;
                    p ^= p << 1; p ^= p << 2; p ^= p << 4; p ^= p << 8; p ^= p << 16;
                    cnt += __popc(p ^ (par ? 0xFFFFFFFFu : 0u));
                    par ^= (int)(p >> 31);
                }
                TC_WAIT_LD();
                if (cc + 2 < 8) TC_LD_X32(rA, D_T + (cc+2)*32);
                {
                    uint32_t word = 0;
#pragma unroll
                    for (int jj = 0; jj < 32; jj++) {
                        float thr = fmaf(-cv, ws[(cc+1)*32+jj], thr0[(cc+1)*32+jj]);
                        if (__uint_as_float(rB[jj]) > thr) word |= (1u << jj);
                    }
                    uint32_t p = word;
                    p ^= p << 1; p ^= p << 2; p ^= p << 4; p ^= p << 8; p ^= p << 16;
                    cnt += __popc(p ^ (par ? 0xFFFFFFFFu : 0u));
                    par ^= (int)(p >> 31);
                }
            }
            g_gf[g*M_ + m0 + row] = (float)cnt * (1.0f/256.0f);
            TC_FENCE_BEFORE();
            asm volatile("bar.sync 1, 128;" ::: "memory");
            if (tid == 128 && g < 3) MBAR_ARRIVE(BAR_DFREE);
        }
    }

    __syncthreads();
    if (tid == 0) {
#pragma unroll
        for (int s = 0; s < 4; s++) { MBAR_INVAL(BAR_FULL(s)); MBAR_INVAL(BAR_EMPTY(s)); }
        MBAR_INVAL(BAR_EPI); MBAR_INVAL(BAR_DFREE);
    }
    __syncthreads();
    if (wid == 0) TC_DEALLOC(tmem, 512);

#else  // ======================= fp32 fallback (compute_103 pass) =======================
    float* xs    = (float*)smem_raw;                 // 128 x 260
    float* ws    = (float*)(smem_raw + 133120);      // 32 x 256
    float* convs = (float*)(smem_raw + 165888);      // 128
    unsigned char* bits = smem_raw + 166400;         // 64 x 264

    const float4* xblk = (const float4*)(x + (size_t)m0 * D_);
#pragma unroll 4
    for (int i = 0; i < 32; i++) {
        int idx = tid + i*256;
        int r = idx >> 6, c = idx & 63;
        *(float4*)(xs + r*260 + c*4) = xblk[idx];
    }
    __syncthreads();

    if (tid < 128) {
        const float* xrow = xs + tid*260;
        int par = 0, cnt = 0;
#pragma unroll 8
        for (int q = 0; q < D_; q++) { par ^= (xrow[q] > 0.0f); cnt += par; }
        convs[tid] = (float)cnt * (1.0f/256.0f);
    }
    __syncthreads();

    const int rowg = tid >> 4;
    const int colg = tid & 15;
    const int r0   = rowg * 4;

    for (int g = 0; g < 4; g++) {
        const float* bias = (g==0)?bfp:(g==1)?bip:(g==2)?bup:bop;
        const float* wsum = g_wsum + g*256;

        for (int rh = 0; rh < 2; rh++) {
            float acc[4][16];
#pragma unroll
            for (int i = 0; i < 4; i++)
#pragma unroll
                for (int j = 0; j < 16; j++) acc[i][j] = 0.0f;

            for (int ks = 0; ks < 8; ks++) {
                float4* d = (float4*)ws;
                const float4* s = (const float4*)(g_Wt + g*65536 + ks*8192);
#pragma unroll
                for (int i = 0; i < 8; i++) d[tid + i*256] = s[tid + i*256];
                __syncthreads();
                const float* xk = xs + (rh*64 + r0)*260 + ks*32;
#pragma unroll 4
                for (int kk = 0; kk < 32; kk++) {
                    float x0 = xk[0*260 + kk];
                    float x1 = xk[1*260 + kk];
                    float x2 = xk[2*260 + kk];
                    float x3 = xk[3*260 + kk];
                    const float* wk = ws + kk*256 + colg;
#pragma unroll
                    for (int j = 0; j < 16; j++) {
                        float wv = wk[j*16];
                        acc[0][j] = fmaf(x0, wv, acc[0][j]);
                        acc[1][j] = fmaf(x1, wv, acc[1][j]);
                        acc[2][j] = fmaf(x2, wv, acc[2][j]);
                        acc[3][j] = fmaf(x3, wv, acc[3][j]);
                    }
                }
                __syncthreads();
            }

            float cv0 = convs[rh*64 + r0 + 0];
            float cv1 = convs[rh*64 + r0 + 1];
            float cv2 = convs[rh*64 + r0 + 2];
            float cv3 = convs[rh*64 + r0 + 3];
#pragma unroll
            for (int j = 0; j < 16; j++) {
                int q = colg + j*16;
                float wq = wsum[q];
                float bq = bias[q];
                bits[(r0+0)*264 + q] = (fmaf(cv0, wq, acc[0][j] + bq) > 0.5f);
                bits[(r0+1)*264 + q] = (fmaf(cv1, wq, acc[1][j] + bq) > 0.5f);
                bits[(r0+2)*264 + q] = (fmaf(cv2, wq, acc[2][j] + bq) > 0.5f);
                bits[(r0+3)*264 + q] = (fmaf(cv3, wq, acc[3][j] + bq) > 0.5f);
            }
            __syncthreads();

            if (tid < 64) {
                const unsigned char* br = bits + tid*264;
                int par = 0, cnt = 0;
#pragma unroll 8
                for (int q = 0; q < Q_; q++) { par ^= br[q]; cnt += par; }
                g_gf[g*M_ + m0 + rh*64 + tid] = (float)cnt * (1.0f/256.0f);
            }
            __syncthreads();
        }
    }
#endif
}

// ============================ K2: scalar scan ============================
__global__ void scan_kernel(const float* __restrict__ cx0)
{
    int b = threadIdx.x;
    float cx = cx0[b * H_];
    float hx = 0.0f;
    const float* pf_ = g_gf;
    const float* pi_ = g_gf + M_;
    const float* pu_ = g_gf + 2*M_;
    const float* po_ = g_gf + 3*M_;
#pragma unroll 8
    for (int t = 0; t < T_; t++) {
        int m = t*B_ + b;
        float f  = 1.0f / (1.0f + expf(-pf_[m]));
        float ii = 1.0f / (1.0f + expf(-pi_[m]));
        float gg = tanhf(pu_[m]);
        float o  = 1.0f / (1.0f + expf(-po_[m]));
        cx = fmaf(f, cx, ii * gg);
        hx = o * tanhf(cx);
        g_hxs[m] = hx;
    }
    g_hxf[b] = hx;
    g_cxf[b] = cx;
}

// ============================ K3: broadcast ============================
__global__ void bcast_kernel(float4* __restrict__ out)
{
    unsigned int i = blockIdx.x * 256u + threadIdx.x;
    const unsigned int OUTS_F4 = (unsigned int)(T_) * B_ * (H_/4);
    float v;
    if (i < OUTS_F4) {
        v = g_hxs[i >> 6];
    } else {
        unsigned int j = i - OUTS_F4;
        if (j < (unsigned int)(B_*H_/4)) v = g_hxf[j >> 6];
        else                             v = g_cxf[(j - B_*H_/4) >> 6];
    }
    __stcs(&out[i], make_float4(v, v, v, v));
}

// ============================ launch ============================
extern "C" void kernel_launch(void* const* d_in, const int* in_sizes, int n_in,
                              void* d_out, int out_size)
{
    const float* x   = (const float*)d_in[0];
    const float* cx0 = (const float*)d_in[2];
    const float* Wf  = (const float*)d_in[3];
    const float* bf_ = (const float*)d_in[4];
    const float* Wi  = (const float*)d_in[5];
    const float* bi_ = (const float*)d_in[6];
    const float* Wu  = (const float*)d_in[7];
    const float* bu_ = (const float*)d_in[8];
    const float* Wo  = (const float*)d_in[9];
    const float* bo_ = (const float*)d_in[10];

    cudaFuncSetAttribute(qmma_kernel, cudaFuncAttributeMaxDynamicSharedMemorySize, SMEM_DYN);

    prep_kernel<<<1024, 256>>>(Wf, Wi, Wu, Wo);
    qmma_kernel<<<NTILES, 256, SMEM_DYN>>>(x, bf_, bi_, bu_, bo_);
    scan_kernel<<<1, B_>>>(cx0);

    const unsigned int total_f4 = (unsigned int)(T_) * B_ * (H_/4) + 2u * (B_*H_/4);
    bcast_kernel<<<total_f4 / 256, 256>>>((float4*)d_out);
}

// round 5
// speedup vs baseline: 3.1643x; 1.1830x over previous
#include <cuda_runtime.h>
#include <cuda_bf16.h>
#include <cuda_fp16.h>
#include <math.h>
#include <stdint.h>

#define T_ 512
#define B_ 256
#define D_ 256
#define H_ 256
#define Q_ 256
#define M_ (T_*B_)
#define MT 128
#define NTILES (M_/MT)

// tcgen05 only exists in the arch-specific ('a') compilation pass.
#if defined(__CUDA_ARCH__) && (defined(__CUDA_ARCH_FEAT_SM103_ALL) || defined(__CUDA_ARCH_FEAT_SM100_ALL) || defined(__CUDA_ARCH_FEAT_SM110_ALL) || (defined(__CUDA_ARCH_SPECIFIC__) && (__CUDA_ARCH_SPECIFIC__ == 1030 || __CUDA_ARCH_SPECIFIC__ == 1000)))
#define USE_TCGEN05 1
#else
#define USE_TCGEN05 0
#endif

// idesc: dtype F32, atype/btype F16, N=256, M=128
#define IDESC ((1u<<4)|((256u/8)<<17)|((128u/16)<<24))

// ---- scratch (no cudaMalloc allowed) ----
__device__ float g_wsum[4*256];
__device__ float g_Wt[4*256*256];                        // fp32 [gate][k][q] (fallback path)
__device__ float g_gf[4*M_];
__device__ float g_hxs[M_];
__device__ float g_hxf[B_];
__device__ float g_cxf[B_];
__device__ __align__(1024) uint8_t g_Wb[4*2*4*32768];    // [gate][split][kc] 32KB swizzled fp16 chunks

// ---- smem offsets (relative to 1024-aligned base) ----
#define SM_A      0                      // 65536 : x0 SW128
#define SM_W      65536                  // 4 x 32768 ring (also x1 staging in prologue)
#define SM_CONV   196608                 // 128 floats
#define SM_THR    197120                 // 4*256 floats  (0.5 - bias)
#define SM_WS2    201216                 // 4*256 floats  (wsum)
#define SM_TPTR   205312
#define SM_BAR    205328                 // full[4] empty[4] epi dfree
#define SMEM_DYN  206848

#define BAR_FULL(s)  (sb + SM_BAR + (s)*8)
#define BAR_EMPTY(s) (sb + SM_BAR + 32 + (s)*8)
#define BAR_EPI      (sb + SM_BAR + 64)
#define BAR_DFREE    (sb + SM_BAR + 72)

// ============================ common helpers ============================
__device__ __forceinline__ uint32_t smem_u32(const void* p){
    uint32_t a;
    asm("{ .reg .u64 t; cvta.to.shared.u64 t, %1; cvt.u32.u64 %0, t; }" : "=r"(a) : "l"(p));
    return a;
}
__device__ __forceinline__ uint32_t pack_h2(__half a, __half b){
    uint16_t ua = __half_as_ushort(a);
    uint16_t ub = __half_as_ushort(b);
    return (uint32_t)ua | ((uint32_t)ub << 16);
}
__device__ __forceinline__ void split2h(float v, __half& s0, __half& s1){
    s0 = __float2half_rn(v);
    s1 = __float2half_rn(v - __half2float(s0));
}

#if USE_TCGEN05
// ============================ tcgen05 PTX helpers ============================
__device__ __forceinline__ uint32_t elect_one(){
    uint32_t p;
    asm volatile("{\n\t.reg .pred p;\n\telect.sync _|p, 0xFFFFFFFF;\n\tselp.b32 %0,1,0,p;\n\t}":"=r"(p));
    return p;
}
#define MBAR_INIT(a,c) asm volatile("mbarrier.init.shared.b64 [%0], %1;"::"r"(a),"r"(c):"memory")
#define MBAR_INVAL(a)  asm volatile("mbarrier.inval.shared.b64 [%0];"::"r"(a):"memory")
#define MBAR_ARRIVE(a) asm volatile("mbarrier.arrive.shared.b64 _, [%0];"::"r"(a):"memory")
#define MBAR_WAIT(a,ph) do{ uint32_t _m=(a),_p=(ph),_d; \
    asm volatile("{\n\t.reg .pred p;\n\tmbarrier.try_wait.parity.acquire.cta.shared::cta.b64 p,[%1],%2;\n\tselp.b32 %0,1,0,p;\n\t}":"=r"(_d):"r"(_m),"r"(_p):"memory"); \
    if(!_d){ asm volatile("{\n\t.reg .pred P1;\n\tWL_%=:\n\tmbarrier.try_wait.parity.acquire.cta.shared::cta.b64 P1,[%0],%1,0x989680;\n\t@P1 bra.uni WD_%=;\n\tbra.uni WL_%=;\n\tWD_%=:\n\t}"::"r"(_m),"r"(_p):"memory"); } }while(0)
#define MBAR_EXPECT_TX(a,n) asm volatile("mbarrier.arrive.expect_tx.shared.b64 _, [%0], %1;"::"r"(a),"r"(n):"memory")

#define TC_ALLOC(sa,n)   asm volatile("tcgen05.alloc.cta_group::1.sync.aligned.shared::cta.b32 [%0], %1;"::"r"(sa),"r"(n):"memory")
#define TC_DEALLOC(t,n)  asm volatile("tcgen05.dealloc.cta_group::1.sync.aligned.b32 %0, %1;"::"r"(t),"r"(n))
#define TC_COMMIT(a)     asm volatile("tcgen05.commit.cta_group::1.mbarrier::arrive::one.shared::cluster.b64 [%0];"::"r"(a):"memory")
#define TC_FENCE_BEFORE() asm volatile("tcgen05.fence::before_thread_sync;":::"memory")
#define TC_FENCE_AFTER()  asm volatile("tcgen05.fence::after_thread_sync;":::"memory")
#define TC_WAIT_LD()     asm volatile("tcgen05.wait::ld.sync.aligned;":::"memory")
#define TC_WAIT_ST()     asm volatile("tcgen05.wait::st.sync.aligned;":::"memory")
#define FENCE_PROXY()    asm volatile("fence.proxy.async.shared::cta;":::"memory")

#define TC_LD_X32(r, a) \
    asm volatile("tcgen05.ld.sync.aligned.32x32b.x32.b32 " \
        "{%0,%1,%2,%3,%4,%5,%6,%7,%8,%9,%10,%11,%12,%13,%14,%15," \
        "%16,%17,%18,%19,%20,%21,%22,%23,%24,%25,%26,%27,%28,%29,%30,%31}, [%32];" \
        : "=r"((r)[0]),"=r"((r)[1]),"=r"((r)[2]),"=r"((r)[3]),"=r"((r)[4]),"=r"((r)[5]),"=r"((r)[6]),"=r"((r)[7]), \
          "=r"((r)[8]),"=r"((r)[9]),"=r"((r)[10]),"=r"((r)[11]),"=r"((r)[12]),"=r"((r)[13]),"=r"((r)[14]),"=r"((r)[15]), \
          "=r"((r)[16]),"=r"((r)[17]),"=r"((r)[18]),"=r"((r)[19]),"=r"((r)[20]),"=r"((r)[21]),"=r"((r)[22]),"=r"((r)[23]), \
          "=r"((r)[24]),"=r"((r)[25]),"=r"((r)[26]),"=r"((r)[27]),"=r"((r)[28]),"=r"((r)[29]),"=r"((r)[30]),"=r"((r)[31]) \
        : "r"(a))

#define TC_ST_X32(a, r) \
    asm volatile("tcgen05.st.sync.aligned.32x32b.x32.b32 [%0], " \
        "{%1,%2,%3,%4,%5,%6,%7,%8,%9,%10,%11,%12,%13,%14,%15,%16," \
        "%17,%18,%19,%20,%21,%22,%23,%24,%25,%26,%27,%28,%29,%30,%31,%32};" \
        :: "r"(a), \
           "r"((r)[0]),"r"((r)[1]),"r"((r)[2]),"r"((r)[3]),"r"((r)[4]),"r"((r)[5]),"r"((r)[6]),"r"((r)[7]), \
           "r"((r)[8]),"r"((r)[9]),"r"((r)[10]),"r"((r)[11]),"r"((r)[12]),"r"((r)[13]),"r"((r)[14]),"r"((r)[15]), \
           "r"((r)[16]),"r"((r)[17]),"r"((r)[18]),"r"((r)[19]),"r"((r)[20]),"r"((r)[21]),"r"((r)[22]),"r"((r)[23]), \
           "r"((r)[24]),"r"((r)[25]),"r"((r)[26]),"r"((r)[27]),"r"((r)[28]),"r"((r)[29]),"r"((r)[30]),"r"((r)[31]) \
        : "memory")

// SW128 K-major descriptor: layout=2, version=1, SBO=64, LBO=1
static constexpr uint64_t DESC_BASE =
    (uint64_t(2)<<61) | (uint64_t(1)<<46) | (uint64_t(64)<<32) | (uint64_t(1)<<16);
__device__ __forceinline__ uint64_t make_desc(uint32_t addr){
    return DESC_BASE | (uint64_t)((addr>>4)&0x3FFF);
}
__device__ __forceinline__ void mma_ss(uint32_t d, uint64_t a, uint64_t b, uint32_t en){
    asm volatile("{\n\t.reg .pred p;\n\tsetp.ne.u32 p, %4, 0;\n\t"
        "tcgen05.mma.cta_group::1.kind::f16 [%0], %1, %2, %3, {%5,%5,%5,%5}, p;\n\t}"
        :: "r"(d), "l"(a), "l"(b), "r"(IDESC), "r"(en), "r"(0u) : "memory");
}
__device__ __forceinline__ void mma_ts(uint32_t d, uint32_t a_tmem, uint64_t b, uint32_t en){
    asm volatile("{\n\t.reg .pred p;\n\tsetp.ne.u32 p, %4, 0;\n\t"
        "tcgen05.mma.cta_group::1.kind::f16 [%0], [%1], %2, %3, {%5,%5,%5,%5}, p;\n\t}"
        :: "r"(d), "r"(a_tmem), "l"(b), "r"(IDESC), "r"(en), "r"(0u) : "memory");
}
__device__ __forceinline__ void bulk_ld(uint32_t dst, const void* src, uint32_t mbar){
    asm volatile("{\n\t.reg .u64 g;\n\tcvta.to.global.u64 g, %1;\n\t"
        "cp.async.bulk.shared::cluster.global.mbarrier::complete_tx::bytes [%0], [g], %2, [%3];\n\t}"
        :: "r"(dst), "l"(src), "n"(32768), "r"(mbar) : "memory");
}
#endif // USE_TCGEN05

// ============================ K0: weight prep ============================
__global__ void prep_kernel(const float* __restrict__ Wf, const float* __restrict__ Wi,
                            const float* __restrict__ Wu, const float* __restrict__ Wo)
{
    int g = blockIdx.x >> 8;
    int q = blockIdx.x & 255;
    int k = threadIdx.x;
    const float* W = (g==0)?Wf:(g==1)?Wi:(g==2)?Wu:Wo;

    float w = W[q*512 + k];
    g_Wt[(g*256 + k)*256 + q] = w;                       // fp32 for fallback

    __half w0, w1; split2h(w, w0, w1);
    uint32_t off = (uint32_t)((q>>3)*1024 + (q&7)*128 + (k&63)*2);
    off ^= (off>>3) & 0x70;
    int kc = k >> 6;
    *(__half*)(g_Wb + ((size_t)((g*2+0)*4 + kc))*32768 + off) = w0;
    *(__half*)(g_Wb + ((size_t)((g*2+1)*4 + kc))*32768 + off) = w1;

    __shared__ float red[256];
    red[k] = W[q*512 + 256 + k];
    __syncthreads();
    for (int s = 128; s > 0; s >>= 1) {
        if (k < s) red[k] += red[k+s];
        __syncthreads();
    }
    if (k == 0) g_wsum[g*256 + q] = red[0];
}

// ============================ K1: GEMM + parity ============================
__global__ __launch_bounds__(256, 1) void qmma_kernel(
    const float* __restrict__ x,
    const float* __restrict__ bfp, const float* __restrict__ bip,
    const float* __restrict__ bup, const float* __restrict__ bop)
{
    extern __shared__ uint8_t smem_raw[];
    const int tid = threadIdx.x;
    const int m0  = blockIdx.x * MT;

#if USE_TCGEN05
    uint32_t sraw = smem_u32(smem_raw);
    uint32_t sb   = (sraw + 1023u) & ~1023u;
    uint8_t* sm   = smem_raw + (sb - sraw);
    const int wid = tid >> 5;

    if (wid == 0) TC_ALLOC(sb + SM_TPTR, 512);
    if (tid == 0) {
#pragma unroll
        for (int s = 0; s < 4; s++) { MBAR_INIT(BAR_FULL(s), 1); MBAR_INIT(BAR_EMPTY(s), 1); }
        MBAR_INIT(BAR_EPI, 1);
        MBAR_INIT(BAR_DFREE, 1);
    }
    __syncthreads();
    uint32_t tmem;
    asm volatile("ld.shared.b32 %0, [%1];" : "=r"(tmem) : "r"(sb + SM_TPTR));
    const uint32_t D_T  = tmem;        // cols 0..255
    const uint32_t X1_T = tmem + 256;  // cols 256..383

    // ---- prologue: split x (fp16 x2); x0 -> SW128 smem; x1 staged linear in ring area ----
    {
        const float4* xr = (const float4*)(x + (size_t)m0 * D_);
#pragma unroll 4
        for (int i = 0; i < 32; i++) {
            int f4 = tid + i*256;
            int r = f4 >> 6;
            int c = (f4 & 63) * 4;
            float4 v = xr[f4];
            __half a0,a1,a2,a3, b0,b1,b2,b3;
            split2h(v.x, a0,b0); split2h(v.y, a1,b1);
            split2h(v.z, a2,b2); split2h(v.w, a3,b3);
            uint32_t off = (uint32_t)(((r>>3) + (c>>6)*16)*1024 + (r&7)*128 + (c&63)*2);
            uint32_t sw  = off ^ ((off>>3) & 0x70);
            *(uint32_t*)(sm + SM_A + sw)     = pack_h2(a0,a1);
            *(uint32_t*)(sm + SM_A + sw + 4) = pack_h2(a2,a3);
            *(uint32_t*)(sm + SM_W + (size_t)r*512 + c*2)     = pack_h2(b0,b1);
            *(uint32_t*)(sm + SM_W + (size_t)r*512 + c*2 + 4) = pack_h2(b2,b3);
        }
        // thr0 / wsum tables
#pragma unroll
        for (int i = 0; i < 4; i++) {
            int idx = tid + i*256;
            int g2 = idx >> 8, q = idx & 255;
            const float* bg = (g2==0)?bfp:(g2==1)?bip:(g2==2)?bup:bop;
            ((float*)(sm + SM_THR))[idx] = 0.5f - bg[q];
            ((float*)(sm + SM_WS2))[idx] = g_wsum[idx];
        }
    }
    __syncthreads();

    if (wid < 4) {
        uint32_t woff = ((uint32_t)wid) << 21;
#pragma unroll
        for (int cc = 0; cc < 4; cc++) {
            uint32_t r32[32];
#pragma unroll
            for (int j = 0; j < 32; j++)
                r32[j] = *(uint32_t*)(sm + SM_W + (size_t)tid*512 + cc*128 + j*4);
            TC_ST_X32(X1_T + cc*32 + woff, r32);
        }
        TC_WAIT_ST();
        TC_FENCE_BEFORE();
    } else {
        int r = tid - 128;
        const float4* xv = (const float4*)(x + (size_t)(m0 + r) * D_);
        int par = 0, cnt = 0;
#pragma unroll 4
        for (int q4 = 0; q4 < 64; q4++) {
            float4 v = xv[q4];
            par ^= (v.x > 0.0f); cnt += par;
            par ^= (v.y > 0.0f); cnt += par;
            par ^= (v.z > 0.0f); cnt += par;
            par ^= (v.w > 0.0f); cnt += par;
        }
        ((float*)(sm + SM_CONV))[r] = (float)cnt * (1.0f/256.0f);
    }
    FENCE_PROXY();
    __syncthreads();

    // ================= warp-specialized mainloop (no __syncthreads) =================
    // 32 chunks: gate g = c2>>3, idx = c2&7, split s = idx>>2, kc = idx&3.
    if (wid == 2) {
        if ((tid & 31) == 0) {
            // -------- producer: stream 32 weight chunks through 4-slot ring --------
            int pp = 0;
            for (int c2 = 0; c2 < 32; c2++) {
                int slot = c2 & 3;
                if (c2 >= 4) {
                    MBAR_WAIT(BAR_EMPTY(slot), pp);
                    if (slot == 3) pp ^= 1;
                }
                int g = c2 >> 3, idx = c2 & 7, s = idx >> 2, kc = idx & 3;
                const uint8_t* src = g_Wb + ((size_t)((g*2+s)*4 + kc))*32768;
                MBAR_EXPECT_TX(BAR_FULL(slot), 32768u);
                bulk_ld(sb + SM_W + slot*32768, src, BAR_FULL(slot));
            }
        }
    } else if (wid == 0) {
        if (elect_one()) {
            // -------- MMA issuer --------
            TC_FENCE_AFTER();
            const uint64_t adesc = make_desc(sb + SM_A);
            int cp = 0, dp = 0;
            uint32_t en = 0;
            for (int c2 = 0; c2 < 32; c2++) {
                int slot = c2 & 3;
                int g = c2 >> 3, idx = c2 & 7, s = idx >> 2, kc = idx & 3;
                MBAR_WAIT(BAR_FULL(slot), cp);
                if (slot == 3) cp ^= 1;
                if (idx == 0) {
                    if (g > 0) { MBAR_WAIT(BAR_DFREE, dp); dp ^= 1; TC_FENCE_AFTER(); }
                    en = 0;
                }
                uint64_t bd = make_desc(sb + SM_W + slot*32768);
#pragma unroll
                for (int t = 0; t < 4; t++) { mma_ss(D_T, adesc + (uint64_t)(kc*1024 + t*2), bd + t*2, en); en = 1; }
                if (s == 0) {
#pragma unroll
                    for (int t = 0; t < 4; t++) mma_ts(D_T, X1_T + (kc*4 + t)*8, bd + t*2, 1);
                }
                TC_COMMIT(BAR_EMPTY(slot));
                if (idx == 7) TC_COMMIT(BAR_EPI);
            }
        }
    } else if (wid >= 4) {
        // -------- epilogue: per-gate threshold + prefix-parity --------
        const int row = tid - 128;
        const float cv = ((float*)(sm + SM_CONV))[row];
        int ep = 0;
        for (int g = 0; g < 4; g++) {
            MBAR_WAIT(BAR_EPI, ep); ep ^= 1;
            TC_FENCE_AFTER();
            const float* thr0 = (const float*)(sm + SM_THR) + g*256;
            const float* ws   = (const float*)(sm + SM_WS2) + g*256;
            int par = 0, cnt = 0;
            uint32_t rA[32], rB[32];
            TC_LD_X32(rA, D_T);
#pragma unroll
            for (int cc = 0; cc < 8; cc += 2) {
                TC_WAIT_LD();
                TC_LD_X32(rB, D_T + (cc+1)*32);
                {
                    uint32_t word = 0;
#pragma unroll
                    for (int jj = 0; jj < 32; jj++) {
                        float thr = fmaf(-cv, ws[cc*32+jj], thr0[cc*32+jj]);
                        if (__uint_as_float(rA[jj]) > thr) word |= (1u << jj);
                    }
                    uint32_t p = word;
                    p ^= p << 1; p ^= p << 2; p ^= p << 4; p ^= p << 8; p ^= p << 16;
                    cnt += __popc(p ^ (par ? 0xFFFFFFFFu : 0u));
                    par ^= (int)(p >> 31);
                }
                TC_WAIT_LD();
                if (cc + 2 < 8) TC_LD_X32(rA, D_T + (cc+2)*32);
                {
                    uint32_t word = 0;
#pragma unroll
                    for (int jj = 0; jj < 32; jj++) {
                        float thr = fmaf(-cv, ws[(cc+1)*32+jj], thr0[(cc+1)*32+jj]);
                        if (__uint_as_float(rB[jj]) > thr) word |= (1u << jj);
                    }
                    uint32_t p = word;
                    p ^= p << 1; p ^= p << 2; p ^= p << 4; p ^= p << 8; p ^= p << 16;
                    cnt += __popc(p ^ (par ? 0xFFFFFFFFu : 0u));
                    par ^= (int)(p >> 31);
                }
            }
            g_gf[g*M_ + m0 + row] = (float)cnt * (1.0f/256.0f);
            TC_FENCE_BEFORE();
            asm volatile("bar.sync 1, 128;" ::: "memory");
            if (tid == 128 && g < 3) MBAR_ARRIVE(BAR_DFREE);
        }
    }

    __syncthreads();
    if (tid == 0) {
#pragma unroll
        for (int s = 0; s < 4; s++) { MBAR_INVAL(BAR_FULL(s)); MBAR_INVAL(BAR_EMPTY(s)); }
        MBAR_INVAL(BAR_EPI); MBAR_INVAL(BAR_DFREE);
    }
    __syncthreads();
    if (wid == 0) TC_DEALLOC(tmem, 512);

#else  // ======================= fp32 fallback (compute_103 pass) =======================
    float* xs    = (float*)smem_raw;                 // 128 x 260
    float* ws    = (float*)(smem_raw + 133120);      // 32 x 256
    float* convs = (float*)(smem_raw + 165888);      // 128
    unsigned char* bits = smem_raw + 166400;         // 64 x 264

    const float4* xblk = (const float4*)(x + (size_t)m0 * D_);
#pragma unroll 4
    for (int i = 0; i < 32; i++) {
        int idx = tid + i*256;
        int r = idx >> 6, c = idx & 63;
        *(float4*)(xs + r*260 + c*4) = xblk[idx];
    }
    __syncthreads();

    if (tid < 128) {
        const float* xrow = xs + tid*260;
        int par = 0, cnt = 0;
#pragma unroll 8
        for (int q = 0; q < D_; q++) { par ^= (xrow[q] > 0.0f); cnt += par; }
        convs[tid] = (float)cnt * (1.0f/256.0f);
    }
    __syncthreads();

    const int rowg = tid >> 4;
    const int colg = tid & 15;
    const int r0   = rowg * 4;

    for (int g = 0; g < 4; g++) {
        const float* bias = (g==0)?bfp:(g==1)?bip:(g==2)?bup:bop;
        const float* wsum = g_wsum + g*256;

        for (int rh = 0; rh < 2; rh++) {
            float acc[4][16];
#pragma unroll
            for (int i = 0; i < 4; i++)
#pragma unroll
                for (int j = 0; j < 16; j++) acc[i][j] = 0.0f;

            for (int ks = 0; ks < 8; ks++) {
                float4* d = (float4*)ws;
                const float4* s = (const float4*)(g_Wt + g*65536 + ks*8192);
#pragma unroll
                for (int i = 0; i < 8; i++) d[tid + i*256] = s[tid + i*256];
                __syncthreads();
                const float* xk = xs + (rh*64 + r0)*260 + ks*32;
#pragma unroll 4
                for (int kk = 0; kk < 32; kk++) {
                    float x0 = xk[0*260 + kk];
                    float x1 = xk[1*260 + kk];
                    float x2 = xk[2*260 + kk];
                    float x3 = xk[3*260 + kk];
                    const float* wk = ws + kk*256 + colg;
#pragma unroll
                    for (int j = 0; j < 16; j++) {
                        float wv = wk[j*16];
                        acc[0][j] = fmaf(x0, wv, acc[0][j]);
                        acc[1][j] = fmaf(x1, wv, acc[1][j]);
                        acc[2][j] = fmaf(x2, wv, acc[2][j]);
                        acc[3][j] = fmaf(x3, wv, acc[3][j]);
                    }
                }
                __syncthreads();
            }

            float cv0 = convs[rh*64 + r0 + 0];
            float cv1 = convs[rh*64 + r0 + 1];
            float cv2 = convs[rh*64 + r0 + 2];
            float cv3 = convs[rh*64 + r0 + 3];
#pragma unroll
            for (int j = 0; j < 16; j++) {
                int q = colg + j*16;
                float wq = wsum[q];
                float bq = bias[q];
                bits[(r0+0)*264 + q] = (fmaf(cv0, wq, acc[0][j] + bq) > 0.5f);
                bits[(r0+1)*264 + q] = (fmaf(cv1, wq, acc[1][j] + bq) > 0.5f);
                bits[(r0+2)*264 + q] = (fmaf(cv2, wq, acc[2][j] + bq) > 0.5f);
                bits[(r0+3)*264 + q] = (fmaf(cv3, wq, acc[3][j] + bq) > 0.5f);
            }
            __syncthreads();

            if (tid < 64) {
                const unsigned char* br = bits + tid*264;
                int par = 0, cnt = 0;
#pragma unroll 8
                for (int q = 0; q < Q_; q++) { par ^= br[q]; cnt += par; }
                g_gf[g*M_ + m0 + rh*64 + tid] = (float)cnt * (1.0f/256.0f);
            }
            __syncthreads();
        }
    }
#endif
}

// ============================ K2: scalar scan ============================
__global__ void scan_kernel(const float* __restrict__ cx0)
{
    int b = threadIdx.x;
    float cx = cx0[b * H_];
    float hx = 0.0f;
    const float* pf_ = g_gf;
    const float* pi_ = g_gf + M_;
    const float* pu_ = g_gf + 2*M_;
    const float* po_ = g_gf + 3*M_;
#pragma unroll 8
    for (int t = 0; t < T_; t++) {
        int m = t*B_ + b;
        float f  = 1.0f / (1.0f + expf(-pf_[m]));
        float ii = 1.0f / (1.0f + expf(-pi_[m]));
        float gg = tanhf(pu_[m]);
        float o  = 1.0f / (1.0f + expf(-po_[m]));
        cx = fmaf(f, cx, ii * gg);
        hx = o * tanhf(cx);
        g_hxs[m] = hx;
    }
    g_hxf[b] = hx;
    g_cxf[b] = cx;
}

// ============================ K3: broadcast ============================
__global__ void bcast_kernel(float4* __restrict__ out)
{
    unsigned int i = blockIdx.x * 256u + threadIdx.x;
    const unsigned int OUTS_F4 = (unsigned int)(T_) * B_ * (H_/4);
    float v;
    if (i < OUTS_F4) {
        v = g_hxs[i >> 6];
    } else {
        unsigned int j = i - OUTS_F4;
        if (j < (unsigned int)(B_*H_/4)) v = g_hxf[j >> 6];
        else                             v = g_cxf[(j - B_*H_/4) >> 6];
    }
    __stcs(&out[i], make_float4(v, v, v, v));
}

// ============================ launch ============================
extern "C" void kernel_launch(void* const* d_in, const int* in_sizes, int n_in,
                              void* d_out, int out_size)
{
    const float* x   = (const float*)d_in[0];
    const float* cx0 = (const float*)d_in[2];
    const float* Wf  = (const float*)d_in[3];
    const float* bf_ = (const float*)d_in[4];
    const float* Wi  = (const float*)d_in[5];
    const float* bi_ = (const float*)d_in[6];
    const float* Wu  = (const float*)d_in[7];
    const float* bu_ = (const float*)d_in[8];
    const float* Wo  = (const float*)d_in[9];
    const float* bo_ = (const float*)d_in[10];

    cudaFuncSetAttribute(qmma_kernel, cudaFuncAttributeMaxDynamicSharedMemorySize, SMEM_DYN);

    prep_kernel<<<1024, 256>>>(Wf, Wi, Wu, Wo);
    qmma_kernel<<<NTILES, 256, SMEM_DYN>>>(x, bf_, bi_, bu_, bo_);
    scan_kernel<<<1, B_>>>(cx0);

    const unsigned int total_f4 = (unsigned int)(T_) * B_ * (H_/4) + 2u * (B_*H_/4);
    bcast_kernel<<<total_f4 / 256, 256>>>((float4*)d_out);
}

// round 6
// speedup vs baseline: 3.5522x; 1.1226x over previous
#include <cuda_runtime.h>
#include <cuda_bf16.h>
#include <cuda_fp16.h>
#include <math.h>
#include <stdint.h>

#define T_ 512
#define B_ 256
#define D_ 256
#define H_ 256
#define Q_ 256
#define M_ (T_*B_)
#define MT 128
#define NTILES (M_/MT)

// tcgen05 only exists in the arch-specific ('a') compilation pass.
#if defined(__CUDA_ARCH__) && (defined(__CUDA_ARCH_FEAT_SM103_ALL) || defined(__CUDA_ARCH_FEAT_SM100_ALL) || defined(__CUDA_ARCH_FEAT_SM110_ALL) || (defined(__CUDA_ARCH_SPECIFIC__) && (__CUDA_ARCH_SPECIFIC__ == 1030 || __CUDA_ARCH_SPECIFIC__ == 1000)))
#define USE_TCGEN05 1
#else
#define USE_TCGEN05 0
#endif

// idesc: dtype F32, atype/btype F16, N=256, M=128
#define IDESC ((1u<<4)|((256u/8)<<17)|((128u/16)<<24))

// ---- scratch (no cudaMalloc allowed) ----
__device__ float g_wsum[4*256];
__device__ float g_Wt[4*256*256];                        // fp32 [gate][k][q] (fallback path)
__device__ float g_gf[4*M_];
__device__ float g_hxs[M_];
__device__ float g_hxf[B_];
__device__ float g_cxf[B_];
__device__ float g_conv[M_];
__device__ __align__(1024) uint8_t g_Wb[4*2*4*32768];    // [gate][split][kc] 32KB swizzled fp16 chunks
__device__ __align__(1024) uint8_t g_X0[(size_t)M_*D_*2]; // pre-split x0, SW128 64KB tiles
__device__ __align__(1024) uint8_t g_X1[(size_t)M_*D_*2]; // pre-split x1, SW128 64KB tiles

// ---- smem offsets (relative to 1024-aligned base) ----
#define SM_A0     0                      // 65536 : x0 SW128 tile
#define SM_A1     65536                  // 65536 : x1 SW128 tile
#define SM_W      131072                 // 2 x 32768 weight ring
#define SM_CONV   196608                 // 128 floats
#define SM_THR    197120                 // 4*256 floats  (0.5 - bias)
#define SM_WS2    201216                 // 4*256 floats  (wsum)
#define SM_TPTR   205312
#define SM_BAR    205328
#define SMEM_DYN  206848

#define BAR_FULL(s)  (sb + SM_BAR + (s)*8)       // 2 slots
#define BAR_EMPTY(s) (sb + SM_BAR + 16 + (s)*8)  // 2 slots
#define BAR_EPI      (sb + SM_BAR + 32)
#define BAR_DFREE(b) (sb + SM_BAR + 40 + (b)*8)  // 2 buffers
#define BAR_X        (sb + SM_BAR + 56)

// ============================ common helpers ============================
__device__ __forceinline__ uint32_t smem_u32(const void* p){
    uint32_t a;
    asm("{ .reg .u64 t; cvta.to.shared.u64 t, %1; cvt.u32.u64 %0, t; }" : "=r"(a) : "l"(p));
    return a;
}
__device__ __forceinline__ void split2h(float v, __half& s0, __half& s1){
    s0 = __float2half_rn(v);
    s1 = __float2half_rn(v - __half2float(s0));
}
__device__ __forceinline__ uint32_t sw128_tile_off(int r, int c){
    uint32_t off = (uint32_t)(((r>>3) + (c>>6)*16)*1024 + (r&7)*128 + (c&63)*2);
    return off ^ ((off>>3) & 0x70);
}

#if USE_TCGEN05
// ============================ tcgen05 PTX helpers ============================
__device__ __forceinline__ uint32_t elect_one(){
    uint32_t p;
    asm volatile("{\n\t.reg .pred p;\n\telect.sync _|p, 0xFFFFFFFF;\n\tselp.b32 %0,1,0,p;\n\t}":"=r"(p));
    return p;
}
#define MBAR_INIT(a,c) asm volatile("mbarrier.init.shared.b64 [%0], %1;"::"r"(a),"r"(c):"memory")
#define MBAR_INVAL(a)  asm volatile("mbarrier.inval.shared.b64 [%0];"::"r"(a):"memory")
#define MBAR_ARRIVE(a) asm volatile("mbarrier.arrive.shared.b64 _, [%0];"::"r"(a):"memory")
#define MBAR_WAIT(a,ph) do{ uint32_t _m=(a),_p=(ph),_d; \
    asm volatile("{\n\t.reg .pred p;\n\tmbarrier.try_wait.parity.acquire.cta.shared::cta.b64 p,[%1],%2;\n\tselp.b32 %0,1,0,p;\n\t}":"=r"(_d):"r"(_m),"r"(_p):"memory"); \
    if(!_d){ asm volatile("{\n\t.reg .pred P1;\n\tWL_%=:\n\tmbarrier.try_wait.parity.acquire.cta.shared::cta.b64 P1,[%0],%1,0x989680;\n\t@P1 bra.uni WD_%=;\n\tbra.uni WL_%=;\n\tWD_%=:\n\t}"::"r"(_m),"r"(_p):"memory"); } }while(0)
#define MBAR_EXPECT_TX(a,n) asm volatile("mbarrier.arrive.expect_tx.shared.b64 _, [%0], %1;"::"r"(a),"r"(n):"memory")

#define TC_ALLOC(sa,n)   asm volatile("tcgen05.alloc.cta_group::1.sync.aligned.shared::cta.b32 [%0], %1;"::"r"(sa),"r"(n):"memory")
#define TC_DEALLOC(t,n)  asm volatile("tcgen05.dealloc.cta_group::1.sync.aligned.b32 %0, %1;"::"r"(t),"r"(n))
#define TC_COMMIT(a)     asm volatile("tcgen05.commit.cta_group::1.mbarrier::arrive::one.shared::cluster.b64 [%0];"::"r"(a):"memory")
#define TC_FENCE_BEFORE() asm volatile("tcgen05.fence::before_thread_sync;":::"memory")
#define TC_FENCE_AFTER()  asm volatile("tcgen05.fence::after_thread_sync;":::"memory")
#define TC_WAIT_LD()     asm volatile("tcgen05.wait::ld.sync.aligned;":::"memory")
#define FENCE_PROXY()    asm volatile("fence.proxy.async.shared::cta;":::"memory")

#define TC_LD_X32(r, a) \
    asm volatile("tcgen05.ld.sync.aligned.32x32b.x32.b32 " \
        "{%0,%1,%2,%3,%4,%5,%6,%7,%8,%9,%10,%11,%12,%13,%14,%15," \
        "%16,%17,%18,%19,%20,%21,%22,%23,%24,%25,%26,%27,%28,%29,%30,%31}, [%32];" \
        : "=r"((r)[0]),"=r"((r)[1]),"=r"((r)[2]),"=r"((r)[3]),"=r"((r)[4]),"=r"((r)[5]),"=r"((r)[6]),"=r"((r)[7]), \
          "=r"((r)[8]),"=r"((r)[9]),"=r"((r)[10]),"=r"((r)[11]),"=r"((r)[12]),"=r"((r)[13]),"=r"((r)[14]),"=r"((r)[15]), \
          "=r"((r)[16]),"=r"((r)[17]),"=r"((r)[18]),"=r"((r)[19]),"=r"((r)[20]),"=r"((r)[21]),"=r"((r)[22]),"=r"((r)[23]), \
          "=r"((r)[24]),"=r"((r)[25]),"=r"((r)[26]),"=r"((r)[27]),"=r"((r)[28]),"=r"((r)[29]),"=r"((r)[30]),"=r"((r)[31]) \
        : "r"(a))

// SW128 K-major descriptor: layout=2, version=1, SBO=64, LBO=1
static constexpr uint64_t DESC_BASE =
    (uint64_t(2)<<61) | (uint64_t(1)<<46) | (uint64_t(64)<<32) | (uint64_t(1)<<16);
__device__ __forceinline__ uint64_t make_desc(uint32_t addr){
    return DESC_BASE | (uint64_t)((addr>>4)&0x3FFF);
}
__device__ __forceinline__ void mma_ss(uint32_t d, uint64_t a, uint64_t b, uint32_t en){
    asm volatile("{\n\t.reg .pred p;\n\tsetp.ne.u32 p, %4, 0;\n\t"
        "tcgen05.mma.cta_group::1.kind::f16 [%0], %1, %2, %3, {%5,%5,%5,%5}, p;\n\t}"
        :: "r"(d), "l"(a), "l"(b), "r"(IDESC), "r"(en), "r"(0u) : "memory");
}
__device__ __forceinline__ void bulk_ldn(uint32_t dst, const void* src, uint32_t n, uint32_t mbar){
    asm volatile("{\n\t.reg .u64 g;\n\tcvta.to.global.u64 g, %1;\n\t"
        "cp.async.bulk.shared::cluster.global.mbarrier::complete_tx::bytes [%0], [g], %2, [%3];\n\t}"
        :: "r"(dst), "l"(src), "r"(n), "r"(mbar) : "memory");
}
#endif // USE_TCGEN05

// ============================ K0: weight prep ============================
__global__ void prep_kernel(const float* __restrict__ Wf, const float* __restrict__ Wi,
                            const float* __restrict__ Wu, const float* __restrict__ Wo)
{
    int g = blockIdx.x >> 8;
    int q = blockIdx.x & 255;
    int k = threadIdx.x;
    const float* W = (g==0)?Wf:(g==1)?Wi:(g==2)?Wu:Wo;

    float w = W[q*512 + k];
    g_Wt[(g*256 + k)*256 + q] = w;                       // fp32 for fallback

    __half w0, w1; split2h(w, w0, w1);
    uint32_t off = (uint32_t)((q>>3)*1024 + (q&7)*128 + (k&63)*2);
    off ^= (off>>3) & 0x70;
    int kc = k >> 6;
    *(__half*)(g_Wb + ((size_t)((g*2+0)*4 + kc))*32768 + off) = w0;
    *(__half*)(g_Wb + ((size_t)((g*2+1)*4 + kc))*32768 + off) = w1;

    __shared__ float red[256];
    red[k] = W[q*512 + 256 + k];
    __syncthreads();
    for (int s = 128; s > 0; s >>= 1) {
        if (k < s) red[k] += red[k+s];
        __syncthreads();
    }
    if (k == 0) g_wsum[g*256 + q] = red[0];
}

// ============================ K0b: x split + conv (full occupancy) ============================
// One warp per (t,b) row: conv via ballot/popc, fp16x2 exact split, SW128 tile writes.
__global__ __launch_bounds__(256) void xsplit_kernel(const float* __restrict__ x)
{
    int row  = blockIdx.x * 8 + (threadIdx.x >> 5);
    int lane = threadIdx.x & 31;

    const float4* xr = (const float4*)(x + (size_t)row * D_ + lane * 8);
    float4 v0 = xr[0], v1 = xr[1];
    float e[8] = {v0.x, v0.y, v0.z, v0.w, v1.x, v1.y, v1.z, v1.w};

    // conv: prefix-parity fraction of (x > 0) over the row, in index order
    unsigned b = 0;
#pragma unroll
    for (int i = 0; i < 8; i++) b |= (e[i] > 0.0f) ? (1u << i) : 0u;
    unsigned p = b;
    p = (p ^ (p << 1)) & 0xFFu;
    p = (p ^ (p << 2)) & 0xFFu;
    p = (p ^ (p << 4)) & 0xFFu;
    unsigned lane_par = __popc(b) & 1u;
    unsigned mask = __ballot_sync(0xFFFFFFFFu, lane_par);
    unsigned pre  = __popc(mask & ((1u << lane) - 1u)) & 1u;
    int cnt = __popc((p ^ (pre ? 0xFFu : 0u)) & 0xFFu);
#pragma unroll
    for (int o = 16; o > 0; o >>= 1) cnt += __shfl_xor_sync(0xFFFFFFFFu, cnt, o);
    if (lane == 0) g_conv[row] = (float)cnt * (1.0f/256.0f);

    // exact fp16 split, packed converts; write SW128 tile layout
    int tile = row >> 7, r = row & 127;
    size_t base = (size_t)tile * 65536;
#pragma unroll
    for (int k = 0; k < 4; k++) {
        float e0 = e[2*k], e1 = e[2*k+1];
        __half2 h0 = __floats2half2_rn(e0, e1);
        float r0 = e0 - __low2float(h0);
        float r1 = e1 - __high2float(h0);
        __half2 h1 = __floats2half2_rn(r0, r1);
        int c = lane * 8 + 2*k;
        uint32_t sw = sw128_tile_off(r, c);
        *(uint32_t*)(g_X0 + base + sw) = *(uint32_t*)&h0;
        *(uint32_t*)(g_X1 + base + sw) = *(uint32_t*)&h1;
    }
}

// ============================ K1: GEMM + parity ============================
__global__ __launch_bounds__(256, 1) void qmma_kernel(
    const float* __restrict__ x,
    const float* __restrict__ bfp, const float* __restrict__ bip,
    const float* __restrict__ bup, const float* __restrict__ bop)
{
    extern __shared__ uint8_t smem_raw[];
    const int tid = threadIdx.x;
    const int m0  = blockIdx.x * MT;

#if USE_TCGEN05
    uint32_t sraw = smem_u32(smem_raw);
    uint32_t sb   = (sraw + 1023u) & ~1023u;
    uint8_t* sm   = smem_raw + (sb - sraw);
    const int wid = tid >> 5;

    if (wid == 0) TC_ALLOC(sb + SM_TPTR, 512);
    if (tid == 0) {
        MBAR_INIT(BAR_FULL(0),1); MBAR_INIT(BAR_FULL(1),1);
        MBAR_INIT(BAR_EMPTY(0),1); MBAR_INIT(BAR_EMPTY(1),1);
        MBAR_INIT(BAR_EPI,1);
        MBAR_INIT(BAR_DFREE(0),1); MBAR_INIT(BAR_DFREE(1),1);
        MBAR_INIT(BAR_X,1);
    }
    __syncthreads();
    uint32_t tmem;
    asm volatile("ld.shared.b32 %0, [%1];" : "=r"(tmem) : "r"(sb + SM_TPTR));

    // ---- prologue: TMA pre-split x tiles; load conv + tables ----
    if (tid == 0) {
        MBAR_EXPECT_TX(BAR_X, 131072u);
        bulk_ldn(sb + SM_A0, g_X0 + (size_t)blockIdx.x * 65536, 65536u, BAR_X);
        bulk_ldn(sb + SM_A1, g_X1 + (size_t)blockIdx.x * 65536, 65536u, BAR_X);
    }
    if (tid >= 128) {
        ((float*)(sm + SM_CONV))[tid - 128] = g_conv[m0 + tid - 128];
    }
#pragma unroll
    for (int i = 0; i < 4; i++) {
        int idx = tid + i*256;
        int g2 = idx >> 8, q = idx & 255;
        const float* bg = (g2==0)?bfp:(g2==1)?bip:(g2==2)?bup:bop;
        ((float*)(sm + SM_THR))[idx] = 0.5f - bg[q];
        ((float*)(sm + SM_WS2))[idx] = g_wsum[idx];
    }
    __syncthreads();

    // ================= warp-specialized mainloop =================
    // 32 chunks: g = c2>>3; idx = c2&7; s = idx&1 (w-split); kc = idx>>1.
    if (wid == 2) {
        if ((tid & 31) == 0) {
            int pp = 0;
            for (int c2 = 0; c2 < 32; c2++) {
                int slot = c2 & 1;
                if (c2 >= 2) {
                    MBAR_WAIT(BAR_EMPTY(slot), pp);
                    if (slot == 1) pp ^= 1;
                }
                int g = c2 >> 3, idx = c2 & 7, s = idx & 1, kc = idx >> 1;
                const uint8_t* src = g_Wb + ((size_t)((g*2+s)*4 + kc))*32768;
                MBAR_EXPECT_TX(BAR_FULL(slot), 32768u);
                bulk_ldn(sb + SM_W + slot*32768, src, 32768u, BAR_FULL(slot));
            }
        }
    } else if (wid == 0) {
        if (elect_one()) {
            MBAR_WAIT(BAR_X, 0);
            TC_FENCE_AFTER();
            const uint64_t a0desc = make_desc(sb + SM_A0);
            const uint64_t a1desc = make_desc(sb + SM_A1);
            int cp = 0;
            uint32_t en = 0;
            for (int c2 = 0; c2 < 32; c2++) {
                int slot = c2 & 1;
                int g = c2 >> 3, idx = c2 & 7, s = idx & 1, kc = idx >> 1;
                MBAR_WAIT(BAR_FULL(slot), cp);
                if (slot == 1) cp ^= 1;
                if (idx == 0) {
                    if (g >= 2) { MBAR_WAIT(BAR_DFREE(g & 1), 0); TC_FENCE_AFTER(); }
                    en = 0;
                }
                uint32_t dT = tmem + (uint32_t)(g & 1) * 256;
                uint64_t bd = make_desc(sb + SM_W + slot*32768);
#pragma unroll
                for (int t = 0; t < 4; t++) { mma_ss(dT, a0desc + (uint64_t)(kc*1024 + t*2), bd + t*2, en); en = 1; }
                if (s == 0) {
#pragma unroll
                    for (int t = 0; t < 4; t++) mma_ss(dT, a1desc + (uint64_t)(kc*1024 + t*2), bd + t*2, 1);
                }
                TC_COMMIT(BAR_EMPTY(slot));
                if (idx == 7) TC_COMMIT(BAR_EPI);
            }
        }
    } else if (wid >= 4) {
        // -------- epilogue (overlaps next gate's MMA via D ping-pong) --------
        const int row = tid - 128;
        const float cv = ((float*)(sm + SM_CONV))[row];
        int ep = 0;
        for (int g = 0; g < 4; g++) {
            MBAR_WAIT(BAR_EPI, ep); ep ^= 1;
            TC_FENCE_AFTER();
            const uint32_t dT = tmem + (uint32_t)(g & 1) * 256;
            const float* thr0 = (const float*)(sm + SM_THR) + g*256;
            const float* ws   = (const float*)(sm + SM_WS2) + g*256;
            int par = 0, cnt = 0;
            uint32_t rA[32], rB[32];
            TC_LD_X32(rA, dT);
#pragma unroll
            for (int cc = 0; cc < 8; cc += 2) {
                TC_WAIT_LD();
                TC_LD_X32(rB, dT + (cc+1)*32);
                {
                    uint32_t word = 0;
#pragma unroll
                    for (int jj = 0; jj < 32; jj++) {
                        float thr = fmaf(-cv, ws[cc*32+jj], thr0[cc*32+jj]);
                        if (__uint_as_float(rA[jj]) > thr) word |= (1u << jj);
                    }
                    uint32_t p = word;
                    p ^= p << 1; p ^= p << 2; p ^= p << 4; p ^= p << 8; p ^= p << 16;
                    cnt += __popc(p ^ (par ? 0xFFFFFFFFu : 0u));
                    par ^= (int)(p >> 31);
                }
                TC_WAIT_LD();
                if (cc + 2 < 8) TC_LD_X32(rA, dT + (cc+2)*32);
                {
                    uint32_t word = 0;
#pragma unroll
                    for (int jj = 0; jj < 32; jj++) {
                        float thr = fmaf(-cv, ws[(cc+1)*32+jj], thr0[(cc+1)*32+jj]);
                        if (__uint_as_float(rB[jj]) > thr) word |= (1u << jj);
                    }
                    uint32_t p = word;
                    p ^= p << 1; p ^= p << 2; p ^= p << 4; p ^= p << 8; p ^= p << 16;
                    cnt += __popc(p ^ (par ? 0xFFFFFFFFu : 0u));
                    par ^= (int)(p >> 31);
                }
            }
            g_gf[g*M_ + m0 + row] = (float)cnt * (1.0f/256.0f);
            TC_FENCE_BEFORE();
            asm volatile("bar.sync 1, 128;" ::: "memory");
            if (tid == 128 && g < 2) MBAR_ARRIVE(BAR_DFREE(g & 1));
        }
    }

    __syncthreads();
    if (tid == 0) {
        MBAR_INVAL(BAR_FULL(0)); MBAR_INVAL(BAR_FULL(1));
        MBAR_INVAL(BAR_EMPTY(0)); MBAR_INVAL(BAR_EMPTY(1));
        MBAR_INVAL(BAR_EPI);
        MBAR_INVAL(BAR_DFREE(0)); MBAR_INVAL(BAR_DFREE(1));
        MBAR_INVAL(BAR_X);
    }
    __syncthreads();
    if (wid == 0) TC_DEALLOC(tmem, 512);

#else  // ======================= fp32 fallback (compute_103 pass) =======================
    float* xs    = (float*)smem_raw;                 // 128 x 260
    float* ws    = (float*)(smem_raw + 133120);      // 32 x 256
    float* convs = (float*)(smem_raw + 165888);      // 128
    unsigned char* bits = smem_raw + 166400;         // 64 x 264

    const float4* xblk = (const float4*)(x + (size_t)m0 * D_);
#pragma unroll 4
    for (int i = 0; i < 32; i++) {
        int idx = tid + i*256;
        int r = idx >> 6, c = idx & 63;
        *(float4*)(xs + r*260 + c*4) = xblk[idx];
    }
    __syncthreads();

    if (tid < 128) {
        const float* xrow = xs + tid*260;
        int par = 0, cnt = 0;
#pragma unroll 8
        for (int q = 0; q < D_; q++) { par ^= (xrow[q] > 0.0f); cnt += par; }
        convs[tid] = (float)cnt * (1.0f/256.0f);
    }
    __syncthreads();

    const int rowg = tid >> 4;
    const int colg = tid & 15;
    const int r0   = rowg * 4;

    for (int g = 0; g < 4; g++) {
        const float* bias = (g==0)?bfp:(g==1)?bip:(g==2)?bup:bop;
        const float* wsum = g_wsum + g*256;

        for (int rh = 0; rh < 2; rh++) {
            float acc[4][16];
#pragma unroll
            for (int i = 0; i < 4; i++)
#pragma unroll
                for (int j = 0; j < 16; j++) acc[i][j] = 0.0f;

            for (int ks = 0; ks < 8; ks++) {
                float4* d = (float4*)ws;
                const float4* s = (const float4*)(g_Wt + g*65536 + ks*8192);
#pragma unroll
                for (int i = 0; i < 8; i++) d[tid + i*256] = s[tid + i*256];
                __syncthreads();
                const float* xk = xs + (rh*64 + r0)*260 + ks*32;
#pragma unroll 4
                for (int kk = 0; kk < 32; kk++) {
                    float x0 = xk[0*260 + kk];
                    float x1 = xk[1*260 + kk];
                    float x2 = xk[2*260 + kk];
                    float x3 = xk[3*260 + kk];
                    const float* wk = ws + kk*256 + colg;
#pragma unroll
                    for (int j = 0; j < 16; j++) {
                        float wv = wk[j*16];
                        acc[0][j] = fmaf(x0, wv, acc[0][j]);
                        acc[1][j] = fmaf(x1, wv, acc[1][j]);
                        acc[2][j] = fmaf(x2, wv, acc[2][j]);
                        acc[3][j] = fmaf(x3, wv, acc[3][j]);
                    }
                }
                __syncthreads();
            }

            float cv0 = convs[rh*64 + r0 + 0];
            float cv1 = convs[rh*64 + r0 + 1];
            float cv2 = convs[rh*64 + r0 + 2];
            float cv3 = convs[rh*64 + r0 + 3];
#pragma unroll
            for (int j = 0; j < 16; j++) {
                int q = colg + j*16;
                float wq = wsum[q];
                float bq = bias[q];
                bits[(r0+0)*264 + q] = (fmaf(cv0, wq, acc[0][j] + bq) > 0.5f);
                bits[(r0+1)*264 + q] = (fmaf(cv1, wq, acc[1][j] + bq) > 0.5f);
                bits[(r0+2)*264 + q] = (fmaf(cv2, wq, acc[2][j] + bq) > 0.5f);
                bits[(r0+3)*264 + q] = (fmaf(cv3, wq, acc[3][j] + bq) > 0.5f);
            }
            __syncthreads();

            if (tid < 64) {
                const unsigned char* br = bits + tid*264;
                int par = 0, cnt = 0;
#pragma unroll 8
                for (int q = 0; q < Q_; q++) { par ^= br[q]; cnt += par; }
                g_gf[g*M_ + m0 + rh*64 + tid] = (float)cnt * (1.0f/256.0f);
            }
            __syncthreads();
        }
    }
#endif
}

// ============================ K2: scalar scan ============================
__global__ void scan_kernel(const float* __restrict__ cx0)
{
    int b = threadIdx.x;
    float cx = cx0[b * H_];
    float hx = 0.0f;
    const float* pf_ = g_gf;
    const float* pi_ = g_gf + M_;
    const float* pu_ = g_gf + 2*M_;
    const float* po_ = g_gf + 3*M_;
#pragma unroll 8
    for (int t = 0; t < T_; t++) {
        int m = t*B_ + b;
        float f  = 1.0f / (1.0f + expf(-pf_[m]));
        float ii = 1.0f / (1.0f + expf(-pi_[m]));
        float gg = tanhf(pu_[m]);
        float o  = 1.0f / (1.0f + expf(-po_[m]));
        cx = fmaf(f, cx, ii * gg);
        hx = o * tanhf(cx);
        g_hxs[m] = hx;
    }
    g_hxf[b] = hx;
    g_cxf[b] = cx;
}

// ============================ K3: broadcast ============================
__global__ void bcast_kernel(float4* __restrict__ out)
{
    unsigned int i = blockIdx.x * 256u + threadIdx.x;
    const unsigned int OUTS_F4 = (unsigned int)(T_) * B_ * (H_/4);
    float v;
    if (i < OUTS_F4) {
        v = g_hxs[i >> 6];
    } else {
        unsigned int j = i - OUTS_F4;
        if (j < (unsigned int)(B_*H_/4)) v = g_hxf[j >> 6];
        else                             v = g_cxf[(j - B_*H_/4) >> 6];
    }
    __stcs(&out[i], make_float4(v, v, v, v));
}

// ============================ launch ============================
extern "C" void kernel_launch(void* const* d_in, const int* in_sizes, int n_in,
                              void* d_out, int out_size)
{
    const float* x   = (const float*)d_in[0];
    const float* cx0 = (const float*)d_in[2];
    const float* Wf  = (const float*)d_in[3];
    const float* bf_ = (const float*)d_in[4];
    const float* Wi  = (const float*)d_in[5];
    const float* bi_ = (const float*)d_in[6];
    const float* Wu  = (const float*)d_in[7];
    const float* bu_ = (const float*)d_in[8];
    const float* Wo  = (const float*)d_in[9];
    const float* bo_ = (const float*)d_in[10];

    cudaFuncSetAttribute(qmma_kernel, cudaFuncAttributeMaxDynamicSharedMemorySize, SMEM_DYN);

    prep_kernel<<<1024, 256>>>(Wf, Wi, Wu, Wo);
    xsplit_kernel<<<M_/8, 256>>>(x);
    qmma_kernel<<<NTILES, 256, SMEM_DYN>>>(x, bf_, bi_, bu_, bo_);
    scan_kernel<<<1, B_>>>(cx0);

    const unsigned int total_f4 = (unsigned int)(T_) * B_ * (H_/4) + 2u * (B_*H_/4);
    bcast_kernel<<<total_f4 / 256, 256>>>((float4*)d_out);
}

// round 7
// speedup vs baseline: 10.4113x; 2.9309x over previous
#include <cuda_runtime.h>
#include <cuda_bf16.h>
#include <cuda_fp16.h>
#include <math.h>
#include <stdint.h>

#define T_ 512
#define B_ 256
#define D_ 256
#define H_ 256
#define Q_ 256
#define M_ (T_*B_)
#define MT 128
#define NTILES (M_/MT)

// tcgen05 only exists in the arch-specific ('a') compilation pass.
#if defined(__CUDA_ARCH__) && (defined(__CUDA_ARCH_FEAT_SM103_ALL) || defined(__CUDA_ARCH_FEAT_SM100_ALL) || defined(__CUDA_ARCH_FEAT_SM110_ALL) || (defined(__CUDA_ARCH_SPECIFIC__) && (__CUDA_ARCH_SPECIFIC__ == 1030 || __CUDA_ARCH_SPECIFIC__ == 1000)))
#define USE_TCGEN05 1
#else
#define USE_TCGEN05 0
#endif

// idesc: dtype F32, atype/btype F16, N=256, M=128
#define IDESC ((1u<<4)|((256u/8)<<17)|((128u/16)<<24))

// ---- scratch (no cudaMalloc allowed) ----
__device__ float g_wsum[4*256];
__device__ float g_Wt[4*256*256];                        // fp32 [gate][k][q] (fallback path)
__device__ float g_gf[4*M_];
__device__ float g_hxs[M_];
__device__ float g_hxf[B_];
__device__ float g_cxf[B_];
__device__ float g_conv[M_];
__device__ __align__(1024) uint8_t g_Wb[4*2*4*32768];    // [gate][split][kc] 32KB swizzled fp16 chunks
__device__ __align__(1024) uint8_t g_X0[(size_t)M_*D_*2]; // pre-split x0, SW128 64KB tiles
__device__ __align__(1024) uint8_t g_X1[(size_t)M_*D_*2]; // pre-split x1, SW128 64KB tiles

// ---- smem offsets (relative to 1024-aligned base) ----
#define SM_A0     0                      // 65536 : x0 SW128 tile
#define SM_A1     65536                  // 65536 : x1 SW128 tile
#define SM_W      131072                 // 2 x 32768 weight ring
#define SM_CONV   196608                 // 128 floats
#define SM_THR    197120                 // 4*256 floats  (0.5 - bias)
#define SM_WS2    201216                 // 4*256 floats  (wsum)
#define SM_TPTR   205312
#define SM_BAR    205328
#define SMEM_DYN  206848

#define BAR_FULL(s)  (sb + SM_BAR + (s)*8)       // 2 slots
#define BAR_EMPTY(s) (sb + SM_BAR + 16 + (s)*8)  // 2 slots
#define BAR_EPI      (sb + SM_BAR + 32)
#define BAR_DFREE(b) (sb + SM_BAR + 40 + (b)*8)  // 2 buffers
#define BAR_X        (sb + SM_BAR + 56)

// ============================ common helpers ============================
__device__ __forceinline__ uint32_t smem_u32(const void* p){
    uint32_t a;
    asm("{ .reg .u64 t; cvta.to.shared.u64 t, %1; cvt.u32.u64 %0, t; }" : "=r"(a) : "l"(p));
    return a;
}
__device__ __forceinline__ void split2h(float v, __half& s0, __half& s1){
    s0 = __float2half_rn(v);
    s1 = __float2half_rn(v - __half2float(s0));
}
__device__ __forceinline__ uint32_t sw128_tile_off(int r, int c){
    uint32_t off = (uint32_t)(((r>>3) + (c>>6)*16)*1024 + (r&7)*128 + (c&63)*2);
    return off ^ ((off>>3) & 0x70);
}

#if USE_TCGEN05
// ============================ tcgen05 PTX helpers ============================
__device__ __forceinline__ uint32_t elect_one(){
    uint32_t p;
    asm volatile("{\n\t.reg .pred p;\n\telect.sync _|p, 0xFFFFFFFF;\n\tselp.b32 %0,1,0,p;\n\t}":"=r"(p));
    return p;
}
#define MBAR_INIT(a,c) asm volatile("mbarrier.init.shared.b64 [%0], %1;"::"r"(a),"r"(c):"memory")
#define MBAR_INVAL(a)  asm volatile("mbarrier.inval.shared.b64 [%0];"::"r"(a):"memory")
#define MBAR_ARRIVE(a) asm volatile("mbarrier.arrive.shared.b64 _, [%0];"::"r"(a):"memory")
#define MBAR_WAIT(a,ph) do{ uint32_t _m=(a),_p=(ph),_d; \
    asm volatile("{\n\t.reg .pred p;\n\tmbarrier.try_wait.parity.acquire.cta.shared::cta.b64 p,[%1],%2;\n\tselp.b32 %0,1,0,p;\n\t}":"=r"(_d):"r"(_m),"r"(_p):"memory"); \
    if(!_d){ asm volatile("{\n\t.reg .pred P1;\n\tWL_%=:\n\tmbarrier.try_wait.parity.acquire.cta.shared::cta.b64 P1,[%0],%1,0x989680;\n\t@P1 bra.uni WD_%=;\n\tbra.uni WL_%=;\n\tWD_%=:\n\t}"::"r"(_m),"r"(_p):"memory"); } }while(0)
#define MBAR_EXPECT_TX(a,n) asm volatile("mbarrier.arrive.expect_tx.shared.b64 _, [%0], %1;"::"r"(a),"r"(n):"memory")

#define TC_ALLOC(sa,n)   asm volatile("tcgen05.alloc.cta_group::1.sync.aligned.shared::cta.b32 [%0], %1;"::"r"(sa),"r"(n):"memory")
#define TC_DEALLOC(t,n)  asm volatile("tcgen05.dealloc.cta_group::1.sync.aligned.b32 %0, %1;"::"r"(t),"r"(n))
#define TC_COMMIT(a)     asm volatile("tcgen05.commit.cta_group::1.mbarrier::arrive::one.shared::cluster.b64 [%0];"::"r"(a):"memory")
#define TC_FENCE_BEFORE() asm volatile("tcgen05.fence::before_thread_sync;":::"memory")
#define TC_FENCE_AFTER()  asm volatile("tcgen05.fence::after_thread_sync;":::"memory")
#define TC_WAIT_LD()     asm volatile("tcgen05.wait::ld.sync.aligned;":::"memory")
#define FENCE_PROXY()    asm volatile("fence.proxy.async.shared::cta;":::"memory")

#define TC_LD_X32(r, a) \
    asm volatile("tcgen05.ld.sync.aligned.32x32b.x32.b32 " \
        "{%0,%1,%2,%3,%4,%5,%6,%7,%8,%9,%10,%11,%12,%13,%14,%15," \
        "%16,%17,%18,%19,%20,%21,%22,%23,%24,%25,%26,%27,%28,%29,%30,%31}, [%32];" \
        : "=r"((r)[0]),"=r"((r)[1]),"=r"((r)[2]),"=r"((r)[3]),"=r"((r)[4]),"=r"((r)[5]),"=r"((r)[6]),"=r"((r)[7]), \
          "=r"((r)[8]),"=r"((r)[9]),"=r"((r)[10]),"=r"((r)[11]),"=r"((r)[12]),"=r"((r)[13]),"=r"((r)[14]),"=r"((r)[15]), \
          "=r"((r)[16]),"=r"((r)[17]),"=r"((r)[18]),"=r"((r)[19]),"=r"((r)[20]),"=r"((r)[21]),"=r"((r)[22]),"=r"((r)[23]), \
          "=r"((r)[24]),"=r"((r)[25]),"=r"((r)[26]),"=r"((r)[27]),"=r"((r)[28]),"=r"((r)[29]),"=r"((r)[30]),"=r"((r)[31]) \
        : "r"(a))

// SW128 K-major descriptor: layout=2, version=1, SBO=64, LBO=1
static constexpr uint64_t DESC_BASE =
    (uint64_t(2)<<61) | (uint64_t(1)<<46) | (uint64_t(64)<<32) | (uint64_t(1)<<16);
__device__ __forceinline__ uint64_t make_desc(uint32_t addr){
    return DESC_BASE | (uint64_t)((addr>>4)&0x3FFF);
}
__device__ __forceinline__ void mma_ss(uint32_t d, uint64_t a, uint64_t b, uint32_t en){
    asm volatile("{\n\t.reg .pred p;\n\tsetp.ne.u32 p, %4, 0;\n\t"
        "tcgen05.mma.cta_group::1.kind::f16 [%0], %1, %2, %3, {%5,%5,%5,%5}, p;\n\t}"
        :: "r"(d), "l"(a), "l"(b), "r"(IDESC), "r"(en), "r"(0u) : "memory");
}
__device__ __forceinline__ void bulk_ldn(uint32_t dst, const void* src, uint32_t n, uint32_t mbar){
    asm volatile("{\n\t.reg .u64 g;\n\tcvta.to.global.u64 g, %1;\n\t"
        "cp.async.bulk.shared::cluster.global.mbarrier::complete_tx::bytes [%0], [g], %2, [%3];\n\t}"
        :: "r"(dst), "l"(src), "r"(n), "r"(mbar) : "memory");
}
#endif // USE_TCGEN05

// ============================ K0: weight prep ============================
__global__ void prep_kernel(const float* __restrict__ Wf, const float* __restrict__ Wi,
                            const float* __restrict__ Wu, const float* __restrict__ Wo)
{
    int g = blockIdx.x >> 8;
    int q = blockIdx.x & 255;
    int k = threadIdx.x;
    const float* W = (g==0)?Wf:(g==1)?Wi:(g==2)?Wu:Wo;

    float w = W[q*512 + k];
    g_Wt[(g*256 + k)*256 + q] = w;                       // fp32 for fallback

    __half w0, w1; split2h(w, w0, w1);
    uint32_t off = (uint32_t)((q>>3)*1024 + (q&7)*128 + (k&63)*2);
    off ^= (off>>3) & 0x70;
    int kc = k >> 6;
    *(__half*)(g_Wb + ((size_t)((g*2+0)*4 + kc))*32768 + off) = w0;
    *(__half*)(g_Wb + ((size_t)((g*2+1)*4 + kc))*32768 + off) = w1;

    __shared__ float red[256];
    red[k] = W[q*512 + 256 + k];
    __syncthreads();
    for (int s = 128; s > 0; s >>= 1) {
        if (k < s) red[k] += red[k+s];
        __syncthreads();
    }
    if (k == 0) g_wsum[g*256 + q] = red[0];
}

// ============================ K0b: x split + conv (full occupancy) ============================
// One warp per (t,b) row: conv via ballot/popc, fp16x2 exact split, SW128 tile writes.
__global__ __launch_bounds__(256) void xsplit_kernel(const float* __restrict__ x)
{
    int row  = blockIdx.x * 8 + (threadIdx.x >> 5);
    int lane = threadIdx.x & 31;

    const float4* xr = (const float4*)(x + (size_t)row * D_ + lane * 8);
    float4 v0 = xr[0], v1 = xr[1];
    float e[8] = {v0.x, v0.y, v0.z, v0.w, v1.x, v1.y, v1.z, v1.w};

    // conv: prefix-parity fraction of (x > 0) over the row, in index order
    unsigned b = 0;
#pragma unroll
    for (int i = 0; i < 8; i++) b |= (e[i] > 0.0f) ? (1u << i) : 0u;
    unsigned p = b;
    p = (p ^ (p << 1)) & 0xFFu;
    p = (p ^ (p << 2)) & 0xFFu;
    p = (p ^ (p << 4)) & 0xFFu;
    unsigned lane_par = __popc(b) & 1u;
    unsigned mask = __ballot_sync(0xFFFFFFFFu, lane_par);
    unsigned pre  = __popc(mask & ((1u << lane) - 1u)) & 1u;
    int cnt = __popc((p ^ (pre ? 0xFFu : 0u)) & 0xFFu);
#pragma unroll
    for (int o = 16; o > 0; o >>= 1) cnt += __shfl_xor_sync(0xFFFFFFFFu, cnt, o);
    if (lane == 0) g_conv[row] = (float)cnt * (1.0f/256.0f);

    // exact fp16 split, packed converts; write SW128 tile layout
    int tile = row >> 7, r = row & 127;
    size_t base = (size_t)tile * 65536;
#pragma unroll
    for (int k = 0; k < 4; k++) {
        float e0 = e[2*k], e1 = e[2*k+1];
        __half2 h0 = __floats2half2_rn(e0, e1);
        float r0 = e0 - __low2float(h0);
        float r1 = e1 - __high2float(h0);
        __half2 h1 = __floats2half2_rn(r0, r1);
        int c = lane * 8 + 2*k;
        uint32_t sw = sw128_tile_off(r, c);
        *(uint32_t*)(g_X0 + base + sw) = *(uint32_t*)&h0;
        *(uint32_t*)(g_X1 + base + sw) = *(uint32_t*)&h1;
    }
}

// ============================ K1: GEMM + parity ============================
__global__ __launch_bounds__(256, 1) void qmma_kernel(
    const float* __restrict__ x,
    const float* __restrict__ bfp, const float* __restrict__ bip,
    const float* __restrict__ bup, const float* __restrict__ bop)
{
    extern __shared__ uint8_t smem_raw[];
    const int tid = threadIdx.x;
    const int m0  = blockIdx.x * MT;

#if USE_TCGEN05
    uint32_t sraw = smem_u32(smem_raw);
    uint32_t sb   = (sraw + 1023u) & ~1023u;
    uint8_t* sm   = smem_raw + (sb - sraw);
    const int wid = tid >> 5;

    if (wid == 0) TC_ALLOC(sb + SM_TPTR, 512);
    if (tid == 0) {
        MBAR_INIT(BAR_FULL(0),1); MBAR_INIT(BAR_FULL(1),1);
        MBAR_INIT(BAR_EMPTY(0),1); MBAR_INIT(BAR_EMPTY(1),1);
        MBAR_INIT(BAR_EPI,1);
        MBAR_INIT(BAR_DFREE(0),1); MBAR_INIT(BAR_DFREE(1),1);
        MBAR_INIT(BAR_X,1);
    }
    __syncthreads();
    uint32_t tmem;
    asm volatile("ld.shared.b32 %0, [%1];" : "=r"(tmem) : "r"(sb + SM_TPTR));

    // ---- prologue: TMA pre-split x tiles; load conv + tables ----
    if (tid == 0) {
        MBAR_EXPECT_TX(BAR_X, 131072u);
        bulk_ldn(sb + SM_A0, g_X0 + (size_t)blockIdx.x * 65536, 65536u, BAR_X);
        bulk_ldn(sb + SM_A1, g_X1 + (size_t)blockIdx.x * 65536, 65536u, BAR_X);
    }
    if (tid >= 128) {
        ((float*)(sm + SM_CONV))[tid - 128] = g_conv[m0 + tid - 128];
    }
#pragma unroll
    for (int i = 0; i < 4; i++) {
        int idx = tid + i*256;
        int g2 = idx >> 8, q = idx & 255;
        const float* bg = (g2==0)?bfp:(g2==1)?bip:(g2==2)?bup:bop;
        ((float*)(sm + SM_THR))[idx] = 0.5f - bg[q];
        ((float*)(sm + SM_WS2))[idx] = g_wsum[idx];
    }
    __syncthreads();

    // ================= warp-specialized mainloop =================
    // 32 chunks: g = c2>>3; idx = c2&7; s = idx&1 (w-split); kc = idx>>1.
    if (wid == 2) {
        if ((tid & 31) == 0) {
            int pp = 0;
            for (int c2 = 0; c2 < 32; c2++) {
                int slot = c2 & 1;
                if (c2 >= 2) {
                    MBAR_WAIT(BAR_EMPTY(slot), pp);
                    if (slot == 1) pp ^= 1;
                }
                int g = c2 >> 3, idx = c2 & 7, s = idx & 1, kc = idx >> 1;
                const uint8_t* src = g_Wb + ((size_t)((g*2+s)*4 + kc))*32768;
                MBAR_EXPECT_TX(BAR_FULL(slot), 32768u);
                bulk_ldn(sb + SM_W + slot*32768, src, 32768u, BAR_FULL(slot));
            }
        }
    } else if (wid == 0) {
        if (elect_one()) {
            MBAR_WAIT(BAR_X, 0);
            TC_FENCE_AFTER();
            const uint64_t a0desc = make_desc(sb + SM_A0);
            const uint64_t a1desc = make_desc(sb + SM_A1);
            int cp = 0;
            uint32_t en = 0;
            for (int c2 = 0; c2 < 32; c2++) {
                int slot = c2 & 1;
                int g = c2 >> 3, idx = c2 & 7, s = idx & 1, kc = idx >> 1;
                MBAR_WAIT(BAR_FULL(slot), cp);
                if (slot == 1) cp ^= 1;
                if (idx == 0) {
                    if (g >= 2) { MBAR_WAIT(BAR_DFREE(g & 1), 0); TC_FENCE_AFTER(); }
                    en = 0;
                }
                uint32_t dT = tmem + (uint32_t)(g & 1) * 256;
                uint64_t bd = make_desc(sb + SM_W + slot*32768);
#pragma unroll
                for (int t = 0; t < 4; t++) { mma_ss(dT, a0desc + (uint64_t)(kc*1024 + t*2), bd + t*2, en); en = 1; }
                if (s == 0) {
#pragma unroll
                    for (int t = 0; t < 4; t++) mma_ss(dT, a1desc + (uint64_t)(kc*1024 + t*2), bd + t*2, 1);
                }
                TC_COMMIT(BAR_EMPTY(slot));
                if (idx == 7) TC_COMMIT(BAR_EPI);
            }
        }
    } else if (wid >= 4) {
        // -------- epilogue (overlaps next gate's MMA via D ping-pong) --------
        const int row = tid - 128;
        const float cv = ((float*)(sm + SM_CONV))[row];
        int ep = 0;
        for (int g = 0; g < 4; g++) {
            MBAR_WAIT(BAR_EPI, ep); ep ^= 1;
            TC_FENCE_AFTER();
            const uint32_t dT = tmem + (uint32_t)(g & 1) * 256;
            const float* thr0 = (const float*)(sm + SM_THR) + g*256;
            const float* ws   = (const float*)(sm + SM_WS2) + g*256;
            int par = 0, cnt = 0;
            uint32_t rA[32], rB[32];
            TC_LD_X32(rA, dT);
#pragma unroll
            for (int cc = 0; cc < 8; cc += 2) {
                TC_WAIT_LD();
                TC_LD_X32(rB, dT + (cc+1)*32);
                {
                    uint32_t word = 0;
#pragma unroll
                    for (int jj = 0; jj < 32; jj++) {
                        float thr = fmaf(-cv, ws[cc*32+jj], thr0[cc*32+jj]);
                        if (__uint_as_float(rA[jj]) > thr) word |= (1u << jj);
                    }
                    uint32_t p = word;
                    p ^= p << 1; p ^= p << 2; p ^= p << 4; p ^= p << 8; p ^= p << 16;
                    cnt += __popc(p ^ (par ? 0xFFFFFFFFu : 0u));
                    par ^= (int)(p >> 31);
                }
                TC_WAIT_LD();
                if (cc + 2 < 8) TC_LD_X32(rA, dT + (cc+2)*32);
                {
                    uint32_t word = 0;
#pragma unroll
                    for (int jj = 0; jj < 32; jj++) {
                        float thr = fmaf(-cv, ws[(cc+1)*32+jj], thr0[(cc+1)*32+jj]);
                        if (__uint_as_float(rB[jj]) > thr) word |= (1u << jj);
                    }
                    uint32_t p = word;
                    p ^= p << 1; p ^= p << 2; p ^= p << 4; p ^= p << 8; p ^= p << 16;
                    cnt += __popc(p ^ (par ? 0xFFFFFFFFu : 0u));
                    par ^= (int)(p >> 31);
                }
            }
            g_gf[g*M_ + m0 + row] = (float)cnt * (1.0f/256.0f);
            TC_FENCE_BEFORE();
            asm volatile("bar.sync 1, 128;" ::: "memory");
            if (tid == 128 && g < 2) MBAR_ARRIVE(BAR_DFREE(g & 1));
        }
    }

    __syncthreads();
    if (tid == 0) {
        MBAR_INVAL(BAR_FULL(0)); MBAR_INVAL(BAR_FULL(1));
        MBAR_INVAL(BAR_EMPTY(0)); MBAR_INVAL(BAR_EMPTY(1));
        MBAR_INVAL(BAR_EPI);
        MBAR_INVAL(BAR_DFREE(0)); MBAR_INVAL(BAR_DFREE(1));
        MBAR_INVAL(BAR_X);
    }
    __syncthreads();
    if (wid == 0) TC_DEALLOC(tmem, 512);

#else  // ======================= fp32 fallback (compute_103 pass) =======================
    float* xs    = (float*)smem_raw;                 // 128 x 260
    float* ws    = (float*)(smem_raw + 133120);      // 32 x 256
    float* convs = (float*)(smem_raw + 165888);      // 128
    unsigned char* bits = smem_raw + 166400;         // 64 x 264

    const float4* xblk = (const float4*)(x + (size_t)m0 * D_);
#pragma unroll 4
    for (int i = 0; i < 32; i++) {
        int idx = tid + i*256;
        int r = idx >> 6, c = idx & 63;
        *(float4*)(xs + r*260 + c*4) = xblk[idx];
    }
    __syncthreads();

    if (tid < 128) {
        const float* xrow = xs + tid*260;
        int par = 0, cnt = 0;
#pragma unroll 8
        for (int q = 0; q < D_; q++) { par ^= (xrow[q] > 0.0f); cnt += par; }
        convs[tid] = (float)cnt * (1.0f/256.0f);
    }
    __syncthreads();

    const int rowg = tid >> 4;
    const int colg = tid & 15;
    const int r0   = rowg * 4;

    for (int g = 0; g < 4; g++) {
        const float* bias = (g==0)?bfp:(g==1)?bip:(g==2)?bup:bop;
        const float* wsum = g_wsum + g*256;

        for (int rh = 0; rh < 2; rh++) {
            float acc[4][16];
#pragma unroll
            for (int i = 0; i < 4; i++)
#pragma unroll
                for (int j = 0; j < 16; j++) acc[i][j] = 0.0f;

            for (int ks = 0; ks < 8; ks++) {
                float4* d = (float4*)ws;
                const float4* s = (const float4*)(g_Wt + g*65536 + ks*8192);
#pragma unroll
                for (int i = 0; i < 8; i++) d[tid + i*256] = s[tid + i*256];
                __syncthreads();
                const float* xk = xs + (rh*64 + r0)*260 + ks*32;
#pragma unroll 4
                for (int kk = 0; kk < 32; kk++) {
                    float x0 = xk[0*260 + kk];
                    float x1 = xk[1*260 + kk];
                    float x2 = xk[2*260 + kk];
                    float x3 = xk[3*260 + kk];
                    const float* wk = ws + kk*256 + colg;
#pragma unroll
                    for (int j = 0; j < 16; j++) {
                        float wv = wk[j*16];
                        acc[0][j] = fmaf(x0, wv, acc[0][j]);
                        acc[1][j] = fmaf(x1, wv, acc[1][j]);
                        acc[2][j] = fmaf(x2, wv, acc[2][j]);
                        acc[3][j] = fmaf(x3, wv, acc[3][j]);
                    }
                }
                __syncthreads();
            }

            float cv0 = convs[rh*64 + r0 + 0];
            float cv1 = convs[rh*64 + r0 + 1];
            float cv2 = convs[rh*64 + r0 + 2];
            float cv3 = convs[rh*64 + r0 + 3];
#pragma unroll
            for (int j = 0; j < 16; j++) {
                int q = colg + j*16;
                float wq = wsum[q];
                float bq = bias[q];
                bits[(r0+0)*264 + q] = (fmaf(cv0, wq, acc[0][j] + bq) > 0.5f);
                bits[(r0+1)*264 + q] = (fmaf(cv1, wq, acc[1][j] + bq) > 0.5f);
                bits[(r0+2)*264 + q] = (fmaf(cv2, wq, acc[2][j] + bq) > 0.5f);
                bits[(r0+3)*264 + q] = (fmaf(cv3, wq, acc[3][j] + bq) > 0.5f);
            }
            __syncthreads();

            if (tid < 64) {
                const unsigned char* br = bits + tid*264;
                int par = 0, cnt = 0;
#pragma unroll 8
                for (int q = 0; q < Q_; q++) { par ^= br[q]; cnt += par; }
                g_gf[g*M_ + m0 + rh*64 + tid] = (float)cnt * (1.0f/256.0f);
            }
            __syncthreads();
        }
    }
#endif
}

// ============================ K2: scalar scan (parallelized) ============================
// One block per batch row b. Gate nonlinearities computed by all 256 threads in
// parallel (the expensive part); only the 512-step cx recurrence is serial
// (thread 0, ~2k cycles from smem); hx/outputs parallel again.
__global__ __launch_bounds__(256) void scan_kernel(const float* __restrict__ cx0)
{
    __shared__ float sa[T_];   // sigmoid(f)
    __shared__ float sbv[T_];  // sigmoid(i)*tanh(g)
    __shared__ float so[T_];   // sigmoid(o)
    __shared__ float scx[T_];  // cx[t]

    const int b   = blockIdx.x;
    const int tid = threadIdx.x;

    // parallel nonlinearities: each thread handles t = tid and t = tid + 256
#pragma unroll
    for (int h = 0; h < 2; h++) {
        int t = tid + h*256;
        int m = t*B_ + b;
        float f  = 1.0f / (1.0f + expf(-g_gf[m]));
        float ii = 1.0f / (1.0f + expf(-g_gf[M_ + m]));
        float gg = tanhf(g_gf[2*M_ + m]);
        float o  = 1.0f / (1.0f + expf(-g_gf[3*M_ + m]));
        sa[t]  = f;
        sbv[t] = ii * gg;
        so[t]  = o;
    }
    __syncthreads();

    // serial recurrence (only true dependency): cx = f*cx + i*g
    if (tid == 0) {
        float cx = cx0[b * H_];
#pragma unroll 8
        for (int t = 0; t < T_; t++) {
            cx = fmaf(sa[t], cx, sbv[t]);
            scx[t] = cx;
        }
        g_cxf[b] = cx;
    }
    __syncthreads();

    // parallel hx
#pragma unroll
    for (int h = 0; h < 2; h++) {
        int t = tid + h*256;
        float hx = so[t] * tanhf(scx[t]);
        g_hxs[t*B_ + b] = hx;
        if (t == T_ - 1) g_hxf[b] = hx;
    }
}

// ============================ K3: broadcast ============================
__global__ void bcast_kernel(float4* __restrict__ out)
{
    unsigned int i = blockIdx.x * 256u + threadIdx.x;
    const unsigned int OUTS_F4 = (unsigned int)(T_) * B_ * (H_/4);
    float v;
    if (i < OUTS_F4) {
        v = g_hxs[i >> 6];
    } else {
        unsigned int j = i - OUTS_F4;
        if (j < (unsigned int)(B_*H_/4)) v = g_hxf[j >> 6];
        else                             v = g_cxf[(j - B_*H_/4) >> 6];
    }
    __stcs(&out[i], make_float4(v, v, v, v));
}

// ============================ launch ============================
extern "C" void kernel_launch(void* const* d_in, const int* in_sizes, int n_in,
                              void* d_out, int out_size)
{
    const float* x   = (const float*)d_in[0];
    const float* cx0 = (const float*)d_in[2];
    const float* Wf  = (const float*)d_in[3];
    const float* bf_ = (const float*)d_in[4];
    const float* Wi  = (const float*)d_in[5];
    const float* bi_ = (const float*)d_in[6];
    const float* Wu  = (const float*)d_in[7];
    const float* bu_ = (const float*)d_in[8];
    const float* Wo  = (const float*)d_in[9];
    const float* bo_ = (const float*)d_in[10];

    cudaFuncSetAttribute(qmma_kernel, cudaFuncAttributeMaxDynamicSharedMemorySize, SMEM_DYN);

    prep_kernel<<<1024, 256>>>(Wf, Wi, Wu, Wo);
    xsplit_kernel<<<M_/8, 256>>>(x);
    qmma_kernel<<<NTILES, 256, SMEM_DYN>>>(x, bf_, bi_, bu_, bo_);
    scan_kernel<<<B_, 256>>>(cx0);

    const unsigned int total_f4 = (unsigned int)(T_) * B_ * (H_/4) + 2u * (B_*H_/4);
    bcast_kernel<<<total_f4 / 256, 256>>>((float4*)d_out);
}